// round 9
// baseline (speedup 1.0000x reference)
#include <cuda_runtime.h>
#include <cstdint>
#include <cfloat>

typedef unsigned int u32;

#define N_ROWS  32768
#define C_DIM   256
#define K_CODES 1024
#define NPASS   8          // code passes of 128
#define E2      0.5f       // 2*E; validated in R8

// ---- smem float offsets (k_all) ----
#define OFF_A     0        // 32768: exact z, fragment layout
#define OFF_B     32768    // 12288: 3 B stages x 4096
#define OFF_EN    45056    // 1024
#define OFF_PD    46080    // 8*128
#define OFF_PS    47104
#define OFF_PI    48128
#define OFF_SD    49152    // 2*128
#define OFF_SS    49408
#define OFF_SI    49664
#define OFF_FLIST 49920    // 128
#define OFF_RLIST 50048    // 128
#define OFF_CCNT  50176    // 128
#define OFF_CAND  50304    // 128*8
#define OFF_ZROW  51328    // 256
#define OFF_WD    51584    // 8
#define OFF_WK    51592    // 8
#define OFF_CNT   51600    // 2 ints: nfull, nref
#define OFF_IDX   51604    // 128 ints (safe from esm overlay)
#define OFF_WSUM  51732    // 8
#define OFF_FLAG  51740    // 1 int
#define SMEM_ALL  (51744 * 4)   // 206976 B
// overlays: t2 staging (8448 f) @ OFF_B during fill; esm (64*257 f) @ OFF_B during gather

__device__ float efr[(size_t)(K_CODES / 8) * 32 * 64];  // tf32(-2*emb) B-fragments
__device__ float embT[C_DIM * K_CODES];                 // exact -2*emb transposed
__device__ float g_enorm[K_CODES];
__device__ float g_partial[256];
__device__ int   g_done;

// ---------------- helpers ----------------
__device__ __forceinline__ u32 smem_u32(const void* p) {
    return (u32)__cvta_generic_to_shared(p);
}
__device__ __forceinline__ void cp16(u32 dst, const void* src) {
    asm volatile("cp.async.cg.shared.global [%0], [%1], 16;" :: "r"(dst), "l"(src));
}
__device__ __forceinline__ float tf32_rna(float v) {
    u32 r; asm("cvt.rna.satfinite.tf32.f32 %0, %1;" : "=r"(r) : "f"(v));
    return __uint_as_float(r);
}
__device__ __forceinline__ uint4 cvt4(uint4 a) {
    uint4 o;
    o.x = __float_as_uint(tf32_rna(__uint_as_float(a.x)));
    o.y = __float_as_uint(tf32_rna(__uint_as_float(a.y)));
    o.z = __float_as_uint(tf32_rna(__uint_as_float(a.z)));
    o.w = __float_as_uint(tf32_rna(__uint_as_float(a.w)));
    return o;
}
__device__ __forceinline__ void mma8(float* d, uint4 a, uint2 b) {
    asm("mma.sync.aligned.m16n8k8.row.col.f32.tf32.tf32.f32 "
        "{%0,%1,%2,%3}, {%4,%5,%6,%7}, {%8,%9}, {%0,%1,%2,%3};"
        : "+f"(d[0]), "+f"(d[1]), "+f"(d[2]), "+f"(d[3])
        : "r"(a.x), "r"(a.y), "r"(a.z), "r"(a.w), "r"(b.x), "r"(b.y));
}
__device__ __forceinline__ void upd(float& b1, float& b2, int& i1, float v, int k) {
    if (v < b1 || (v == b1 && k < i1)) { b2 = b1; b1 = v; i1 = k; }
    else if (v < b2) b2 = v;
}
// A-fragment float index for exact-z reads in post phases
__device__ __forceinline__ int idxA(int r, int c) {
    return (((c >> 3) * 8 + (r >> 4)) << 7) + (((r & 7) << 2) + (c & 3)) * 4
           + ((r >> 3) & 1) + (((c >> 2) & 1) << 1);
}

// ---------------------------------------------------------------------------
// prep: efr fragments + embT + norms (128 blocks of 8 codes)
// ---------------------------------------------------------------------------
__global__ void __launch_bounds__(256)
k_prep(const float* __restrict__ emb)
{
    const int tid = threadIdx.x;
    const int ct = blockIdx.x;        // code tile (8 codes)
    const int k0 = ct * 8;
    if (ct == 0 && tid == 0) g_done = 0;
    for (int j = tid; j < 2048; j += 256) {
        int within = j & 63, kt = j >> 6;
        int lane = within >> 1, reg = within & 1;
        int code = k0 + (lane >> 2);
        int cmod = kt * 8 + (lane & 3) + reg * 4;
        efr[(size_t)(ct * 32 + kt) * 64 + within] = tf32_rna(-2.0f * emb[code * C_DIM + cmod]);
    }
    for (int j = tid; j < 2048; j += 256) {
        int c = j >> 3, kk = j & 7;
        embT[c * K_CODES + k0 + kk] = -2.0f * emb[(k0 + kk) * C_DIM + c];
    }
    int wid = tid >> 5, lane = tid & 31;
    int code = k0 + wid;
    const float4* p = (const float4*)(emb + code * C_DIM);
    float4 a = p[lane];
    float4 b = p[lane + 32];
    float s = a.x*a.x + a.y*a.y + a.z*a.z + a.w*a.w
            + b.x*b.x + b.y*b.y + b.z*b.z + b.w*b.w;
    #pragma unroll
    for (int m = 16; m; m >>= 1) s += __shfl_xor_sync(0xffffffffu, s, m);
    if (lane == 0) g_enorm[code] = s;
}

// ---------------------------------------------------------------------------
// fused kernel: fill z -> MMA argmin -> refine/rescue -> gather/res/loss
// CTA = 128 rows, 256 threads, grid 256.
// ---------------------------------------------------------------------------
__global__ void __launch_bounds__(256, 1)
k_all(const float* __restrict__ z_e, const float* __restrict__ emb,
      float* __restrict__ res, float* __restrict__ out_idx_f,
      float* __restrict__ out_loss)
{
    extern __shared__ float smf[];
    float* A   = smf + OFF_A;
    float* en  = smf + OFF_EN;
    float* pd  = smf + OFF_PD;
    float* ps  = smf + OFF_PS;
    int*   pi  = (int*)(smf + OFF_PI);
    float* sd  = smf + OFF_SD;
    float* ss  = smf + OFF_SS;
    int*   sii = (int*)(smf + OFF_SI);
    int*   flist = (int*)(smf + OFF_FLIST);
    int*   rlist = (int*)(smf + OFF_RLIST);
    int*   ccnt  = (int*)(smf + OFF_CCNT);
    int*   cand  = (int*)(smf + OFF_CAND);
    float* zrow  = smf + OFF_ZROW;
    float* wd    = smf + OFF_WD;
    int*   wk    = (int*)(smf + OFF_WK);
    int*   cnts  = (int*)(smf + OFF_CNT);
    int*   idxs  = (int*)(smf + OFF_IDX);
    float* wsum  = smf + OFF_WSUM;
    int*   flag  = (int*)(smf + OFF_FLAG);

    const int tid = threadIdx.x;
    const int lane = tid & 31, wid = tid >> 5;
    const int warp_m = wid & 3, warp_n = wid >> 2;
    const int r0 = blockIdx.x * 128;
    const int b = r0 >> 10, hw0 = r0 & 1023;
    const u32 base = smem_u32(smf);

    if (tid == 0) { cnts[0] = 0; cnts[1] = 0; }

    // ---- phase 1: fill A (exact fp32, fragment layout), 4 passes of 32 rows
    {
        float* t2 = smf + OFF_B;          // 256 x 33 staging (c-major)
        for (int pr = 0; pr < 4; pr++) {
            if (pr) __syncthreads();
            for (int j = tid; j < 8192; j += 256) {      // coalesced global read
                int c = j >> 5, r = j & 31;
                t2[c * 33 + r] = z_e[(((size_t)(b * C_DIM + c)) << 10) + hw0 + pr * 32 + r];
            }
            __syncthreads();
            for (int s = tid; s < 2048; s += 256) {      // conflict-free STS.128
                int kt = s >> 6, mtl = (s >> 5) & 1, ln = s & 31;
                int rl = mtl * 16 + (ln >> 2);
                int c0 = kt * 8 + (ln & 3);
                float4 val;
                val.x = t2[c0 * 33 + rl];
                val.y = t2[c0 * 33 + rl + 8];
                val.z = t2[(c0 + 4) * 33 + rl];
                val.w = t2[(c0 + 4) * 33 + rl + 8];
                *(float4*)(A + ((kt * 8 + pr * 2 + mtl) << 7) + ln * 4) = val;
            }
        }
        __syncthreads();
        for (int i = tid; i < K_CODES; i += 256) en[i] = g_enorm[i];
    }

    // ---- phase 2: mainloop (8 passes x 8 chunks), 3-stage B ring
    float d[2][8][4];
    #pragma unroll
    for (int m = 0; m < 2; m++)
        #pragma unroll
        for (int n = 0; n < 8; n++)
            #pragma unroll
            for (int q2 = 0; q2 < 4; q2++) d[m][n][q2] = 0.0f;

    // B loader (lambda-ish macro via inline)
    #define LOADB(Q) do { \
        int p_ = (Q) >> 3, ch_ = (Q) & 7, st_ = (Q) % 3; \
        u32 dst_ = base + (u32)(OFF_B + st_ * 4096) * 4u; \
        _Pragma("unroll") \
        for (int t2_ = 0; t2_ < 4; t2_++) { \
            int t_ = tid + t2_ * 256; \
            int tile_ = t_ >> 4, part_ = t_ & 15; \
            int ktl_ = tile_ >> 4, nt_ = tile_ & 15; \
            cp16(dst_ + (u32)((tile_ << 8) + (part_ << 4)), \
                 (const char*)efr + ((((size_t)(p_ * 16 + nt_) * 32 + ch_ * 4 + ktl_) << 8) + (part_ << 4))); \
        } \
        asm volatile("cp.async.commit_group;"); \
    } while (0)

    LOADB(0);
    LOADB(1);

    for (int q = 0; q < 64; q++) {
        const int p = q >> 3, ch = q & 7, st = q % 3;
        if (q < 63) asm volatile("cp.async.wait_group 1;");
        else        asm volatile("cp.async.wait_group 0;");
        __syncthreads();
        if (q + 2 < 64) LOADB(q + 2);

        const float* bS = smf + OFF_B + st * 4096;
        #pragma unroll
        for (int ktl = 0; ktl < 4; ktl++) {
            const int kt = ch * 4 + ktl;
            uint4 a[2];
            uint2 bf[8];
            #pragma unroll
            for (int m = 0; m < 2; m++)
                a[m] = cvt4(*(const uint4*)(A + (((kt * 8 + warp_m * 2 + m) << 7) + lane * 4)));
            #pragma unroll
            for (int n = 0; n < 8; n++)
                bf[n] = *(const uint2*)(bS + (((ktl * 16 + warp_n * 8 + n) << 6) + lane * 2));
            #pragma unroll
            for (int m = 0; m < 2; m++)
                #pragma unroll
                for (int n = 0; n < 8; n++)
                    mma8(d[m][n], a[m], bf[n]);
        }

        if (ch == 7) {
            // epilogue for pass p: best + second best per row
            const int g = lane >> 2, tq = lane & 3;
            const int wm0 = warp_m * 32, wn0 = warp_n * 64;
            #pragma unroll
            for (int m = 0; m < 2; m++) {
                #pragma unroll
                for (int h = 0; h < 2; h++) {
                    float b1 = FLT_MAX, b2 = FLT_MAX; int i1 = 0x7fffffff;
                    #pragma unroll
                    for (int n = 0; n < 8; n++) {
                        int cl = wn0 + n * 8 + 2 * tq;
                        int k0 = p * 128 + cl;
                        float v0 = d[m][n][2 * h]     + en[k0];
                        float v1 = d[m][n][2 * h + 1] + en[k0 + 1];
                        upd(b1, b2, i1, v0, k0);
                        upd(b1, b2, i1, v1, k0 + 1);
                    }
                    #pragma unroll
                    for (int s2 = 1; s2 <= 2; s2 <<= 1) {
                        float ob1 = __shfl_xor_sync(0xffffffffu, b1, s2);
                        float ob2 = __shfl_xor_sync(0xffffffffu, b2, s2);
                        int   oi1 = __shfl_xor_sync(0xffffffffu, i1, s2);
                        if (ob1 < b1 || (ob1 == b1 && oi1 < i1)) {
                            b2 = fminf(b1, ob2); b1 = ob1; i1 = oi1;
                        } else b2 = fminf(b2, ob1);
                    }
                    if (tq == 0) {
                        int rl = wm0 + m * 16 + h * 8 + g;
                        sd[warp_n * 128 + rl] = b1;
                        ss[warp_n * 128 + rl] = b2;
                        sii[warp_n * 128 + rl] = i1;
                    }
                }
            }
            // reset accumulators for next pass
            #pragma unroll
            for (int m = 0; m < 2; m++)
                #pragma unroll
                for (int n = 0; n < 8; n++)
                    #pragma unroll
                    for (int q2 = 0; q2 < 4; q2++) d[m][n][q2] = 0.0f;
            __syncthreads();
            if (tid < 128) {
                float b1 = sd[tid], b2 = ss[tid]; int i1 = sii[tid];
                float ob1 = sd[128 + tid], ob2 = ss[128 + tid]; int oi1 = sii[128 + tid];
                if (ob1 < b1 || (ob1 == b1 && oi1 < i1)) {
                    b2 = fminf(b1, ob2); b1 = ob1; i1 = oi1;
                } else b2 = fminf(b2, ob1);
                pd[p * 128 + tid] = b1;
                ps[p * 128 + tid] = b2;
                pi[p * 128 + tid] = i1;
            }
        }
    }
    __syncthreads();

    // ---- phase 3: classify
    if (tid < 128) {
        float V1 = FLT_MAX; int bi = 0x7fffffff;
        float v1[NPASS], v2[NPASS]; int i1[NPASS];
        #pragma unroll
        for (int p = 0; p < NPASS; p++) {
            v1[p] = pd[p * 128 + tid];
            v2[p] = ps[p * 128 + tid];
            i1[p] = pi[p * 128 + tid];
            if (v1[p] < V1 || (v1[p] == V1 && i1[p] < bi)) { V1 = v1[p]; bi = i1[p]; }
        }
        idxs[tid] = bi;
        float th = V1 + E2;
        bool unc = false; int nc = 0; int cl[NPASS];
        #pragma unroll
        for (int p = 0; p < NPASS; p++) {
            if (v2[p] < th) unc = true;
            if (v1[p] < th) cl[nc++] = i1[p];
        }
        if (unc) {
            flist[atomicAdd(&cnts[0], 1)] = tid;
        } else if (nc > 1) {
            int pq = atomicAdd(&cnts[1], 1);
            rlist[pq] = tid;
            ccnt[tid] = nc;
            #pragma unroll
            for (int q2 = 0; q2 < NPASS; q2++) if (q2 < nc) cand[tid * 8 + q2] = cl[q2];
        }
    }
    __syncthreads();
    const int nfull = cnts[0], nref = cnts[1];

    // ---- phase 4: candidate refine (exact fp32, z from smem)
    for (int j = wid; j < nref; j += 8) {
        int rl = rlist[j];
        float zreg[8];
        #pragma unroll
        for (int cc = 0; cc < 8; cc++)
            zreg[cc] = A[idxA(rl, cc * 32 + lane)];
        int nc = ccnt[rl];
        float bd = FLT_MAX; int bk = 0x7fffffff;
        for (int ci = 0; ci < nc; ci++) {
            int k = cand[rl * 8 + ci];
            const float* er = emb + (size_t)k * C_DIM;
            float acc = 0.0f;
            #pragma unroll
            for (int cc = 0; cc < 8; cc++)
                acc += zreg[cc] * er[cc * 32 + lane];
            #pragma unroll
            for (int m = 16; m; m >>= 1) acc += __shfl_xor_sync(0xffffffffu, acc, m);
            float dd = g_enorm[k] - 2.0f * acc;
            if (dd < bd || (dd == bd && k < bk)) { bd = dd; bk = k; }
        }
        if (lane == 0) idxs[rl] = bk;
    }

    // ---- phase 5: full-scan rescue (exact, via embT)
    for (int j = 0; j < nfull; j++) {
        int rl = flist[j];
        __syncthreads();
        zrow[tid] = A[idxA(rl, tid)];
        __syncthreads();
        float bd = FLT_MAX; int bk = 0x7fffffff;
        #pragma unroll
        for (int gch = 0; gch < 4; gch++) {
            int k = wid * 128 + gch * 32 + lane;
            float acc = 0.0f;
            #pragma unroll 8
            for (int c = 0; c < C_DIM; c++)
                acc = fmaf(zrow[c], embT[c * K_CODES + k], acc);
            float dd = g_enorm[k] + acc;
            if (dd < bd) { bd = dd; bk = k; }
        }
        #pragma unroll
        for (int m = 16; m; m >>= 1) {
            float obd = __shfl_xor_sync(0xffffffffu, bd, m);
            int   obk = __shfl_xor_sync(0xffffffffu, bk, m);
            if (obd < bd || (obd == bd && obk < bk)) { bd = obd; bk = obk; }
        }
        if (lane == 0) { wd[wid] = bd; wk[wid] = bk; }
        __syncthreads();
        if (tid == 0) {
            float B = FLT_MAX; int K = 0x7fffffff;
            #pragma unroll
            for (int w = 0; w < 8; w++)
                if (wd[w] < B || (wd[w] == B && wk[w] < K)) { B = wd[w]; K = wk[w]; }
            idxs[rl] = K;
        }
    }
    __syncthreads();

    if (tid < 128) out_idx_f[r0 + tid] = (float)idxs[tid];

    // ---- phase 6: gather + res + loss (2 half-passes of 64 rows)
    float lacc = 0.0f;
    float* esm = smf + OFF_B;                 // 64 x 257 overlay
    for (int hp = 0; hp < 2; hp++) {
        const int rbase = hp * 64;
        __syncthreads();
        for (int i = tid; i < 64 * 256; i += 256) {
            int r = i >> 8, c = i & 255;
            esm[r * 257 + c] = emb[idxs[rbase + r] * C_DIM + c];
        }
        __syncthreads();
        // res write sweep: coalesced over rows
        {
            const int r = tid & 63, cq = tid >> 6;
            for (int cc = 0; cc < 256; cc += 4) {
                int c = cc + cq;
                res[(((size_t)(b * C_DIM + c)) << 10) + hw0 + rbase + r] = esm[r * 257 + c];
            }
        }
        // loss sweep: warp per 8 rows
        #pragma unroll
        for (int rr = 0; rr < 8; rr++) {
            int lr = wid * 8 + rr;
            #pragma unroll
            for (int cc = 0; cc < 8; cc++) {
                int c = cc * 32 + lane;
                float v = esm[lr * 257 + c];
                float z = A[idxA(rbase + lr, c)];
                float df = v - z;
                lacc += df * df;
            }
        }
    }
    #pragma unroll
    for (int m = 16; m; m >>= 1) lacc += __shfl_xor_sync(0xffffffffu, lacc, m);
    if (lane == 0) wsum[wid] = lacc;
    __syncthreads();
    if (tid == 0) {
        float s = 0.0f;
        #pragma unroll
        for (int w = 0; w < 8; w++) s += wsum[w];
        g_partial[blockIdx.x] = s;
        __threadfence();
        flag[0] = (atomicAdd(&g_done, 1) == 255) ? 1 : 0;
    }
    __syncthreads();
    if (flag[0] && wid == 0) {
        __threadfence();
        float s = 0.0f;
        for (int j = lane; j < 256; j += 32) s += g_partial[j];
        #pragma unroll
        for (int m = 16; m; m >>= 1) s += __shfl_xor_sync(0xffffffffu, s, m);
        if (lane == 0) out_loss[0] = 1.25f * (s / 8388608.0f);
    }
    #undef LOADB
}

// ---------------------------------------------------------------------------
extern "C" void kernel_launch(void* const* d_in, const int* in_sizes, int n_in,
                              void* d_out, int out_size)
{
    const float* z_e = (const float*)d_in[0];
    const float* emb = (const float*)d_in[1];

    float* out  = (float*)d_out;
    float* res  = out;
    float* loss = out + 8388608;
    float* idxf = out + 8388609;

    cudaFuncSetAttribute(k_all, cudaFuncAttributeMaxDynamicSharedMemorySize, SMEM_ALL);

    k_prep <<<128, 256>>>(emb);
    k_all  <<<256, 256, SMEM_ALL>>>(z_e, emb, res, idxf, loss);
}

// round 10
// speedup vs baseline: 1.1752x; 1.1752x over previous
#include <cuda_runtime.h>
#include <cstdint>
#include <cfloat>

typedef unsigned int u32;

#define N_ROWS  32768
#define C_DIM   256
#define K_CODES 1024
#define NCB     8          // code-blocks of 128
#define NCHUNK  8          // chunks of 32 c (K logical = 256, hi*hi only)
#define E2      0.5f       // 2*E; validated R7/R8
#define NSTAGE  3
#define STAGE_BYTES 32768  // A 16KB + B 16KB
#define SMEM_MMA (NSTAGE * STAGE_BYTES)   // 98304 -> 2 CTAs/SM
#define SMEM_POST (128 * 257 * 4)

// fragment-native layouts
// zfr: [row_tile(2048)][kt(32)][lane 32][reg 4]  (tf32 hi)
// efr: [code_tile(128)][kt(32)][lane 32][reg 2]  (tf32 hi of -2*emb)
__device__ float zfr[(size_t)(N_ROWS / 16) * 32 * 128];
__device__ float efr[(size_t)(K_CODES / 8) * 32 * 64];
__device__ float embT[C_DIM * K_CODES];    // [c][k] = -2*emb[k][c], exact fp32
__device__ float g_enorm[K_CODES];
__device__ float g_pd[NCB * N_ROWS];
__device__ float g_ps[NCB * N_ROWS];
__device__ int   g_pi[NCB * N_ROWS];
__device__ float g_partial[256];

// ---------------- helpers ----------------
__device__ __forceinline__ u32 smem_u32(const void* p) {
    return (u32)__cvta_generic_to_shared(p);
}
__device__ __forceinline__ void cp16(u32 dst, const void* src) {
    asm volatile("cp.async.cg.shared.global [%0], [%1], 16;" :: "r"(dst), "l"(src));
}
__device__ __forceinline__ float tf32_rna(float v) {
    u32 r; asm("cvt.rna.satfinite.tf32.f32 %0, %1;" : "=r"(r) : "f"(v));
    return __uint_as_float(r);
}
__device__ __forceinline__ void mma8(float* d, uint4 a, uint2 b) {
    asm("mma.sync.aligned.m16n8k8.row.col.f32.tf32.tf32.f32 "
        "{%0,%1,%2,%3}, {%4,%5,%6,%7}, {%8,%9}, {%0,%1,%2,%3};"
        : "+f"(d[0]), "+f"(d[1]), "+f"(d[2]), "+f"(d[3])
        : "r"(a.x), "r"(a.y), "r"(a.z), "r"(a.w), "r"(b.x), "r"(b.y));
}
__device__ __forceinline__ void upd(float& b1, float& b2, int& i1, float v, int k) {
    if (v < b1 || (v == b1 && k < i1)) { b2 = b1; b1 = v; i1 = k; }
    else if (v < b2) b2 = v;
}

// ---------------------------------------------------------------------------
// prep: blocks [0,1024) convert z; blocks [1024,1152) convert emb (+norms,embT)
// ---------------------------------------------------------------------------
__global__ void __launch_bounds__(256)
k_prep(const float* __restrict__ z_e, const float* __restrict__ emb)
{
    __shared__ float t[32 * 260];
    const int tid = threadIdx.x;
    if (blockIdx.x < 1024) {
        int r0 = blockIdx.x * 32;
        int b = r0 >> 10, hw0 = r0 & 1023;
        for (int i = tid; i < 32 * 256; i += 256) {
            int c = i >> 5, r = i & 31;
            t[r * 260 + c] = z_e[(((size_t)(b * C_DIM + c)) << 10) + hw0 + r];
        }
        __syncthreads();
        int rt0 = r0 >> 4;
        for (int i = tid; i < 32 * 256; i += 256) {
            int within = i & 127;
            int tile = i >> 7;
            int rtl = tile >> 5;
            int kt  = tile & 31;
            int lane = within >> 2, reg = within & 3;
            int rl = rtl * 16 + (lane >> 2) + ((reg & 1) << 3);
            int cmod = (kt << 3) + (lane & 3) + ((reg >> 1) << 2);
            zfr[(((size_t)(rt0 + rtl) * 32 + kt) << 7) + within] = tf32_rna(t[rl * 260 + cmod]);
        }
    } else {
        int ct = blockIdx.x - 1024;        // code tile, 8 codes
        int k0 = ct * 8;
        for (int j = tid; j < 2048; j += 256) {
            int within = j & 63, kt = j >> 6;
            int lane = within >> 1, reg = within & 1;
            int code = k0 + (lane >> 2);
            int cmod = kt * 8 + (lane & 3) + reg * 4;
            efr[(size_t)(ct * 32 + kt) * 64 + within] = tf32_rna(-2.0f * emb[code * C_DIM + cmod]);
        }
        for (int j = tid; j < 2048; j += 256) {
            int c = j >> 3, kk = j & 7;
            embT[c * K_CODES + k0 + kk] = -2.0f * emb[(k0 + kk) * C_DIM + c];
        }
        int wid = tid >> 5, lane = tid & 31;
        int code = k0 + wid;
        const float4* p = (const float4*)(emb + code * C_DIM);
        float4 a = p[lane];
        float4 b = p[lane + 32];
        float s = a.x*a.x + a.y*a.y + a.z*a.z + a.w*a.w
                + b.x*b.x + b.y*b.y + b.z*b.z + b.w*b.w;
        #pragma unroll
        for (int m = 16; m; m >>= 1) s += __shfl_xor_sync(0xffffffffu, s, m);
        if (lane == 0) g_enorm[code] = s;
    }
}

// ---------------------------------------------------------------------------
// main: tf32 mma.sync GEMM (hi*hi) + argmin (best + second-best)
// CTA 128 rows x 128 codes, 8 warps (4 row x 2 col), warp tile 32x64.
// 3-stage cp.async ring, 2 CTAs/SM (proven R6 config, K=256).
// ---------------------------------------------------------------------------
__device__ __forceinline__ void load_chunk(u32 base, int buf, int ch,
                                           int rt0, int cb, int tid)
{
    u32 dst = base + (u32)buf * STAGE_BYTES;
    #pragma unroll
    for (int t2 = 0; t2 < 4; t2++) {           // A: 4kt x 8mt x 512B = 16KB
        int t = tid + t2 * 256;
        int tile = t >> 5, part = t & 31;
        int kt = tile >> 3, mt = tile & 7;
        cp16(dst + (u32)((tile << 9) + (part << 4)),
             (const char*)zfr + ((((size_t)(rt0 + mt) * 32 + ch * 4 + kt) << 9) + (part << 4)));
    }
    #pragma unroll
    for (int t2 = 0; t2 < 4; t2++) {           // B: 4kt x 16nt x 256B = 16KB
        int t = tid + t2 * 256;
        int tile = t >> 4, part = t & 15;
        int kt = tile >> 4, nt = tile & 15;
        cp16(dst + 16384u + (u32)((tile << 8) + (part << 4)),
             (const char*)efr + ((((size_t)(cb * 16 + nt) * 32 + ch * 4 + kt) << 8) + (part << 4)));
    }
    asm volatile("cp.async.commit_group;");
}

__global__ void __launch_bounds__(256, 2)
k_mma()
{
    extern __shared__ float smf[];
    __shared__ float en_s[128];
    __shared__ float sd[2][128], ss[2][128];
    __shared__ int   si[2][128];

    const int tid = threadIdx.x;
    const int lane = tid & 31, wid = tid >> 5;
    const int warp_m = wid & 3, warp_n = wid >> 2;
    const int cb = blockIdx.x;             // fast dim -> L2 reuse of zfr
    const int rb = blockIdx.y;
    const int r0 = rb * 128, rt0 = rb * 8;
    const u32 base = smem_u32(smf);

    if (tid < 128) en_s[tid] = g_enorm[cb * 128 + tid];

    float d[2][8][4];
    #pragma unroll
    for (int m = 0; m < 2; m++)
        #pragma unroll
        for (int n = 0; n < 8; n++)
            #pragma unroll
            for (int q = 0; q < 4; q++) d[m][n][q] = 0.0f;

    load_chunk(base, 0, 0, rt0, cb, tid);
    load_chunk(base, 1, 1, rt0, cb, tid);

    for (int ch = 0; ch < NCHUNK; ch++) {
        int buf = ch % NSTAGE;
        if (ch < NCHUNK - 1) asm volatile("cp.async.wait_group 1;");
        else                 asm volatile("cp.async.wait_group 0;");
        __syncthreads();
        if (ch + 2 < NCHUNK) load_chunk(base, (ch + 2) % NSTAGE, ch + 2, rt0, cb, tid);

        const float* aS = smf + buf * (STAGE_BYTES / 4);
        const float* bS = aS + 4096;
        #pragma unroll
        for (int kt = 0; kt < 4; kt++) {
            uint4 a[2];
            uint2 bf[8];
            #pragma unroll
            for (int m = 0; m < 2; m++)
                a[m] = *(const uint4*)(aS + (((kt * 8 + warp_m * 2 + m) << 7) + (lane << 2)));
            #pragma unroll
            for (int n = 0; n < 8; n++)
                bf[n] = *(const uint2*)(bS + (((kt * 16 + warp_n * 8 + n) << 6) + (lane << 1)));
            #pragma unroll
            for (int m = 0; m < 2; m++)
                #pragma unroll
                for (int n = 0; n < 8; n++)
                    mma8(d[m][n], a[m], bf[n]);
        }
    }

    // epilogue: dist = acc + ||e||^2 ; best + second-best per row
    const int g = lane >> 2, tq = lane & 3;
    const int wm0 = warp_m * 32, wn0 = warp_n * 64;
    #pragma unroll
    for (int m = 0; m < 2; m++) {
        #pragma unroll
        for (int h = 0; h < 2; h++) {
            float b1 = FLT_MAX, b2 = FLT_MAX; int i1 = 0x7fffffff;
            #pragma unroll
            for (int n = 0; n < 8; n++) {
                int cl = wn0 + n * 8 + 2 * tq;
                float v0 = d[m][n][2 * h]     + en_s[cl];
                float v1 = d[m][n][2 * h + 1] + en_s[cl + 1];
                int k0 = cb * 128 + cl;
                upd(b1, b2, i1, v0, k0);
                upd(b1, b2, i1, v1, k0 + 1);
            }
            #pragma unroll
            for (int s = 1; s <= 2; s <<= 1) {
                float ob1 = __shfl_xor_sync(0xffffffffu, b1, s);
                float ob2 = __shfl_xor_sync(0xffffffffu, b2, s);
                int   oi1 = __shfl_xor_sync(0xffffffffu, i1, s);
                if (ob1 < b1 || (ob1 == b1 && oi1 < i1)) {
                    b2 = fminf(b1, ob2); b1 = ob1; i1 = oi1;
                } else b2 = fminf(b2, ob1);
            }
            if (tq == 0) {
                int rl = wm0 + m * 16 + h * 8 + g;
                sd[warp_n][rl] = b1; ss[warp_n][rl] = b2; si[warp_n][rl] = i1;
            }
        }
    }
    __syncthreads();
    if (tid < 128) {
        float b1 = sd[0][tid], b2 = ss[0][tid]; int i1 = si[0][tid];
        float ob1 = sd[1][tid], ob2 = ss[1][tid]; int oi1 = si[1][tid];
        if (ob1 < b1 || (ob1 == b1 && oi1 < i1)) {
            b2 = fminf(b1, ob2); b1 = ob1; i1 = oi1;
        } else b2 = fminf(b2, ob1);
        int row = r0 + tid;
        g_pd[cb * N_ROWS + row] = b1;
        g_ps[cb * N_ROWS + row] = b2;
        g_pi[cb * N_ROWS + row] = i1;
    }
}

// ---------------------------------------------------------------------------
// post: pick + candidate refine + full-scan rescue + gather + loss partial.
// ---------------------------------------------------------------------------
__global__ void __launch_bounds__(256)
k_post(const float* __restrict__ z_e, const float* __restrict__ emb,
       float* __restrict__ res, float* __restrict__ out_idx_f)
{
    extern __shared__ float esm[];           // 128 x 257
    __shared__ int   idx_sm[128];
    __shared__ int   full_list[128];
    __shared__ int   ref_list[128];
    __shared__ int   cand[128][8];
    __shared__ int   ccnt[128];
    __shared__ int   nfull_s, nref_s;
    __shared__ float zrow[256];
    __shared__ float wd[8]; __shared__ int wk[8];
    __shared__ float wsum[8];

    const int tid = threadIdx.x;
    const int wid = tid >> 5, lane = tid & 31;
    const int r0 = blockIdx.x * 128;
    const int b = r0 >> 10, hw0 = r0 & 1023;

    if (tid == 0) { nfull_s = 0; nref_s = 0; }
    __syncthreads();

    // classify
    if (tid < 128) {
        int row = r0 + tid;
        float V1 = FLT_MAX; int bi = 0x7fffffff;
        float v1[8], v2[8]; int i1[8];
        #pragma unroll
        for (int cb = 0; cb < NCB; cb++) {
            v1[cb] = g_pd[cb * N_ROWS + row];
            v2[cb] = g_ps[cb * N_ROWS + row];
            i1[cb] = g_pi[cb * N_ROWS + row];
            if (v1[cb] < V1 || (v1[cb] == V1 && i1[cb] < bi)) { V1 = v1[cb]; bi = i1[cb]; }
        }
        idx_sm[tid] = bi;
        float th = V1 + E2;
        bool unc = false; int nc = 0; int cl[8];
        #pragma unroll
        for (int cb = 0; cb < NCB; cb++) {
            if (v2[cb] < th) unc = true;
            if (v1[cb] < th) cl[nc++] = i1[cb];
        }
        if (unc) {
            full_list[atomicAdd(&nfull_s, 1)] = tid;
        } else if (nc > 1) {
            int p = atomicAdd(&nref_s, 1);
            ref_list[p] = tid;
            ccnt[tid] = nc;
            #pragma unroll
            for (int q = 0; q < 8; q++) if (q < nc) cand[tid][q] = cl[q];
        }
    }
    __syncthreads();

    // candidate refine: warp per entry, exact fp32
    for (int j = wid; j < nref_s; j += 8) {
        int rl = ref_list[j];
        int hw = hw0 + rl;
        float zreg[8];
        #pragma unroll
        for (int cc = 0; cc < 8; cc++)
            zreg[cc] = z_e[(((size_t)(b * C_DIM + cc * 32 + lane)) << 10) + hw];
        int nc = ccnt[rl];
        float bd = FLT_MAX; int bk = 0x7fffffff;
        for (int ci = 0; ci < nc; ci++) {
            int k = cand[rl][ci];
            const float* er = emb + (size_t)k * C_DIM;
            float acc = 0.0f;
            #pragma unroll
            for (int cc = 0; cc < 8; cc++)
                acc += zreg[cc] * er[cc * 32 + lane];
            #pragma unroll
            for (int m = 16; m; m >>= 1) acc += __shfl_xor_sync(0xffffffffu, acc, m);
            float dd = g_enorm[k] - 2.0f * acc;
            if (dd < bd || (dd == bd && k < bk)) { bd = dd; bk = k; }
        }
        if (lane == 0) idx_sm[rl] = bk;
    }

    // full-scan rescue: block-cooperative, coalesced via embT
    int nfull = nfull_s;
    for (int j = 0; j < nfull; j++) {
        int rl = full_list[j];
        __syncthreads();
        zrow[tid] = z_e[(((size_t)(b * C_DIM + tid)) << 10) + hw0 + rl];
        __syncthreads();
        float bd = FLT_MAX; int bk = 0x7fffffff;
        #pragma unroll
        for (int gch = 0; gch < 4; gch++) {
            int k = wid * 128 + gch * 32 + lane;
            float acc = 0.0f;
            #pragma unroll 8
            for (int c = 0; c < C_DIM; c++)
                acc = fmaf(zrow[c], embT[c * K_CODES + k], acc);
            float dd = g_enorm[k] + acc;
            if (dd < bd) { bd = dd; bk = k; }   // k increasing -> ties keep lower k
        }
        #pragma unroll
        for (int m = 16; m; m >>= 1) {
            float obd = __shfl_xor_sync(0xffffffffu, bd, m);
            int   obk = __shfl_xor_sync(0xffffffffu, bk, m);
            if (obd < bd || (obd == bd && obk < bk)) { bd = obd; bk = obk; }
        }
        if (lane == 0) { wd[wid] = bd; wk[wid] = bk; }
        __syncthreads();
        if (tid == 0) {
            float B = FLT_MAX; int K = 0x7fffffff;
            #pragma unroll
            for (int w = 0; w < 8; w++)
                if (wd[w] < B || (wd[w] == B && wk[w] < K)) { B = wd[w]; K = wk[w]; }
            idx_sm[rl] = K;
        }
    }
    __syncthreads();

    if (tid < 128) out_idx_f[r0 + tid] = (float)idx_sm[tid];

    // gather + loss partial
    for (int i = tid; i < 128 * 256; i += 256) {
        int r = i >> 8, c = i & 255;
        esm[r * 257 + c] = emb[idx_sm[r] * C_DIM + c];
    }
    __syncthreads();

    float acc = 0.0f;
    const int r = tid & 127, chalf = tid >> 7;
    for (int cc = 0; cc < 256; cc += 2) {
        int c = cc + chalf;
        float v = esm[r * 257 + c];
        size_t gi = (((size_t)(b * C_DIM + c)) << 10) + hw0 + r;
        float zv = z_e[gi];
        res[gi] = v;
        float df = v - zv;
        acc += df * df;
    }
    #pragma unroll
    for (int m = 16; m; m >>= 1) acc += __shfl_xor_sync(0xffffffffu, acc, m);
    if (lane == 0) wsum[wid] = acc;
    __syncthreads();
    if (tid == 0) {
        float s = 0.0f;
        #pragma unroll
        for (int w = 0; w < 8; w++) s += wsum[w];
        g_partial[blockIdx.x] = s;
    }
}

__global__ void k_loss(float* __restrict__ out_loss) {
    __shared__ float s[256];
    int tid = threadIdx.x;
    s[tid] = g_partial[tid];
    __syncthreads();
    for (int st = 128; st > 0; st >>= 1) {
        if (tid < st) s[tid] += s[tid + st];
        __syncthreads();
    }
    if (tid == 0) out_loss[0] = 1.25f * (s[0] / 8388608.0f);
}

// ---------------------------------------------------------------------------
extern "C" void kernel_launch(void* const* d_in, const int* in_sizes, int n_in,
                              void* d_out, int out_size)
{
    const float* z_e = (const float*)d_in[0];
    const float* emb = (const float*)d_in[1];

    float* out  = (float*)d_out;
    float* res  = out;
    float* loss = out + 8388608;
    float* idxf = out + 8388609;

    cudaFuncSetAttribute(k_mma,  cudaFuncAttributeMaxDynamicSharedMemorySize, SMEM_MMA);
    cudaFuncSetAttribute(k_post, cudaFuncAttributeMaxDynamicSharedMemorySize, SMEM_POST);

    k_prep <<<1152, 256>>>(z_e, emb);
    k_mma  <<<dim3(NCB, N_ROWS / 128), 256, SMEM_MMA>>>();
    k_post <<<N_ROWS / 128, 256, SMEM_POST>>>(z_e, emb, res, idxf);
    k_loss <<<1, 256>>>(loss);
}

// round 11
// speedup vs baseline: 1.2155x; 1.0343x over previous
#include <cuda_runtime.h>
#include <cstdint>
#include <cfloat>

typedef unsigned int u32;

#define N_ROWS  32768
#define C_DIM   256
#define K_CODES 1024
#define NCB     8          // code-blocks of 128
#define NCHUNK  8          // chunks of 32 c (K logical = 256, hi*hi only)
#define E2      0.5f       // 2*E; validated R7/R8/R10
#define NSTAGE  3
#define A_STRIDE 132       // floats per c slice (pad 4 -> conflict-free frag reads)
#define A_FLOATS (32 * A_STRIDE)          // 4224
#define A_BYTES  (A_FLOATS * 4)           // 16896
#define STAGE_BYTES (A_BYTES + 16384)     // 33280
#define SMEM_MMA (NSTAGE * STAGE_BYTES)   // 99840 -> 2 CTAs/SM
#define SMEM_POST (128 * 257 * 4)

// efr: [code_tile(128)][kt(32)][lane 32][reg 2]  (tf32 hi of -2*emb)
__device__ float efr[(size_t)(K_CODES / 8) * 32 * 64];
__device__ float embT[C_DIM * K_CODES];    // [c][k] = -2*emb[k][c], exact fp32
__device__ float g_enorm[K_CODES];
__device__ float g_pd[NCB * N_ROWS];
__device__ float g_ps[NCB * N_ROWS];
__device__ int   g_pi[NCB * N_ROWS];
__device__ float g_partial[256];

// ---------------- helpers ----------------
__device__ __forceinline__ u32 smem_u32(const void* p) {
    return (u32)__cvta_generic_to_shared(p);
}
__device__ __forceinline__ void cp16(u32 dst, const void* src) {
    asm volatile("cp.async.cg.shared.global [%0], [%1], 16;" :: "r"(dst), "l"(src));
}
__device__ __forceinline__ u32 tf32u(float v) {
    u32 r; asm("cvt.rna.satfinite.tf32.f32 %0, %1;" : "=r"(r) : "f"(v));
    return r;
}
__device__ __forceinline__ void mma8(float* d, uint4 a, uint2 b) {
    asm("mma.sync.aligned.m16n8k8.row.col.f32.tf32.tf32.f32 "
        "{%0,%1,%2,%3}, {%4,%5,%6,%7}, {%8,%9}, {%0,%1,%2,%3};"
        : "+f"(d[0]), "+f"(d[1]), "+f"(d[2]), "+f"(d[3])
        : "r"(a.x), "r"(a.y), "r"(a.z), "r"(a.w), "r"(b.x), "r"(b.y));
}
__device__ __forceinline__ void upd(float& b1, float& b2, int& i1, float v, int k) {
    if (v < b1 || (v == b1 && k < i1)) { b2 = b1; b1 = v; i1 = k; }
    else if (v < b2) b2 = v;
}

// ---------------------------------------------------------------------------
// prep (emb only now): efr fragments + embT + norms. 128 blocks of 8 codes.
// ---------------------------------------------------------------------------
__global__ void __launch_bounds__(256)
k_prep(const float* __restrict__ emb)
{
    const int tid = threadIdx.x;
    const int ct = blockIdx.x;        // code tile (8 codes)
    const int k0 = ct * 8;
    for (int j = tid; j < 2048; j += 256) {
        int within = j & 63, kt = j >> 6;
        int lane = within >> 1, reg = within & 1;
        int code = k0 + (lane >> 2);
        int cmod = kt * 8 + (lane & 3) + reg * 4;
        efr[(size_t)(ct * 32 + kt) * 64 + within] =
            __uint_as_float(tf32u(-2.0f * emb[code * C_DIM + cmod]));
    }
    for (int j = tid; j < 2048; j += 256) {
        int c = j >> 3, kk = j & 7;
        embT[c * K_CODES + k0 + kk] = -2.0f * emb[(k0 + kk) * C_DIM + c];
    }
    int wid = tid >> 5, lane = tid & 31;
    int code = k0 + wid;
    const float4* p = (const float4*)(emb + code * C_DIM);
    float4 a = p[lane];
    float4 b = p[lane + 32];
    float s = a.x*a.x + a.y*a.y + a.z*a.z + a.w*a.w
            + b.x*b.x + b.y*b.y + b.z*b.z + b.w*b.w;
    #pragma unroll
    for (int m = 16; m; m >>= 1) s += __shfl_xor_sync(0xffffffffu, s, m);
    if (lane == 0) g_enorm[code] = s;
}

// ---------------------------------------------------------------------------
// main: tf32 mma.sync GEMM (hi*hi) + argmin (best + second-best)
// CTA 128 rows x 128 codes, 8 warps (4 row x 2 col), warp tile 32x64.
// A loaded DIRECTLY from z_e (NCHW is c-major-friendly: 512B contiguous per c),
// stored [c][row] pad-132; tf32 cvt happens in registers. B = efr fragments.
// 3-stage cp.async ring, 2 CTAs/SM.
// ---------------------------------------------------------------------------
__device__ __forceinline__ void load_chunk(u32 base, int buf, int ch,
                                           int b, int hw0, int cb, int tid,
                                           const float* __restrict__ z_e)
{
    u32 dst = base + (u32)buf * STAGE_BYTES;
    #pragma unroll
    for (int t2 = 0; t2 < 4; t2++) {           // A: 32 c x 128 rows, direct from z_e
        int t = tid + t2 * 256;
        int c = t >> 5, part = t & 31;
        cp16(dst + (u32)(c * (A_STRIDE * 4) + part * 16),
             z_e + (((size_t)(b * C_DIM + ch * 32 + c)) << 10) + hw0 + part * 4);
    }
    #pragma unroll
    for (int t2 = 0; t2 < 4; t2++) {           // B: 4kt x 16nt x 256B = 16KB
        int t = tid + t2 * 256;
        int tile = t >> 4, part = t & 15;
        int kt = tile >> 4, nt = tile & 15;
        cp16(dst + (u32)A_BYTES + (u32)((tile << 8) + (part << 4)),
             (const char*)efr + ((((size_t)(cb * 16 + nt) * 32 + ch * 4 + kt) << 8) + (part << 4)));
    }
    asm volatile("cp.async.commit_group;");
}

__global__ void __launch_bounds__(256, 2)
k_mma(const float* __restrict__ z_e)
{
    extern __shared__ float smf[];
    __shared__ float en_s[128];
    __shared__ float sd[2][128], ss[2][128];
    __shared__ int   si[2][128];

    const int tid = threadIdx.x;
    const int lane = tid & 31, wid = tid >> 5;
    const int warp_m = wid & 3, warp_n = wid >> 2;
    const int cb = blockIdx.x;             // fast dim -> L2 reuse of z_e
    const int rb = blockIdx.y;
    const int r0 = rb * 128;
    const int b = r0 >> 10, hw0 = r0 & 1023;
    const u32 base = smem_u32(smf);

    if (tid < 128) en_s[tid] = g_enorm[cb * 128 + tid];

    float d[2][8][4];
    #pragma unroll
    for (int m = 0; m < 2; m++)
        #pragma unroll
        for (int n = 0; n < 8; n++)
            #pragma unroll
            for (int q = 0; q < 4; q++) d[m][n][q] = 0.0f;

    load_chunk(base, 0, 0, b, hw0, cb, tid, z_e);
    load_chunk(base, 1, 1, b, hw0, cb, tid, z_e);

    // per-thread A fragment base indices (c-major, pad 132)
    const int frow = (lane >> 2);          // + warp_m*32 + m*16 (+8 for odd reg)
    const int fc   = (lane & 3);           // + kt*8 (+4 for hi regs)

    for (int ch = 0; ch < NCHUNK; ch++) {
        int buf = ch % NSTAGE;
        if (ch < NCHUNK - 1) asm volatile("cp.async.wait_group 1;");
        else                 asm volatile("cp.async.wait_group 0;");
        __syncthreads();
        if (ch + 2 < NCHUNK) load_chunk(base, (ch + 2) % NSTAGE, ch + 2, b, hw0, cb, tid, z_e);

        const float* aS = smf + buf * (STAGE_BYTES / 4);
        const float* bS = aS + A_FLOATS;
        #pragma unroll
        for (int kt = 0; kt < 4; kt++) {
            uint4 a[2];
            uint2 bf[8];
            #pragma unroll
            for (int m = 0; m < 2; m++) {
                int rbase = warp_m * 32 + m * 16 + frow;
                int cbase = kt * 8 + fc;
                a[m].x = tf32u(aS[ cbase      * A_STRIDE + rbase    ]);
                a[m].y = tf32u(aS[ cbase      * A_STRIDE + rbase + 8]);
                a[m].z = tf32u(aS[(cbase + 4) * A_STRIDE + rbase    ]);
                a[m].w = tf32u(aS[(cbase + 4) * A_STRIDE + rbase + 8]);
            }
            #pragma unroll
            for (int n = 0; n < 8; n++)
                bf[n] = *(const uint2*)(bS + (((kt * 16 + warp_n * 8 + n) << 6) + (lane << 1)));
            #pragma unroll
            for (int m = 0; m < 2; m++)
                #pragma unroll
                for (int n = 0; n < 8; n++)
                    mma8(d[m][n], a[m], bf[n]);
        }
    }

    // epilogue: dist = acc + ||e||^2 ; best + second-best per row
    const int g = lane >> 2, tq = lane & 3;
    const int wm0 = warp_m * 32, wn0 = warp_n * 64;
    #pragma unroll
    for (int m = 0; m < 2; m++) {
        #pragma unroll
        for (int h = 0; h < 2; h++) {
            float b1 = FLT_MAX, b2 = FLT_MAX; int i1 = 0x7fffffff;
            #pragma unroll
            for (int n = 0; n < 8; n++) {
                int cl = wn0 + n * 8 + 2 * tq;
                float v0 = d[m][n][2 * h]     + en_s[cl];
                float v1 = d[m][n][2 * h + 1] + en_s[cl + 1];
                int k0 = cb * 128 + cl;
                upd(b1, b2, i1, v0, k0);
                upd(b1, b2, i1, v1, k0 + 1);
            }
            #pragma unroll
            for (int s = 1; s <= 2; s <<= 1) {
                float ob1 = __shfl_xor_sync(0xffffffffu, b1, s);
                float ob2 = __shfl_xor_sync(0xffffffffu, b2, s);
                int   oi1 = __shfl_xor_sync(0xffffffffu, i1, s);
                if (ob1 < b1 || (ob1 == b1 && oi1 < i1)) {
                    b2 = fminf(b1, ob2); b1 = ob1; i1 = oi1;
                } else b2 = fminf(b2, ob1);
            }
            if (tq == 0) {
                int rl = wm0 + m * 16 + h * 8 + g;
                sd[warp_n][rl] = b1; ss[warp_n][rl] = b2; si[warp_n][rl] = i1;
            }
        }
    }
    __syncthreads();
    if (tid < 128) {
        float b1 = sd[0][tid], b2 = ss[0][tid]; int i1 = si[0][tid];
        float ob1 = sd[1][tid], ob2 = ss[1][tid]; int oi1 = si[1][tid];
        if (ob1 < b1 || (ob1 == b1 && oi1 < i1)) {
            b2 = fminf(b1, ob2); b1 = ob1; i1 = oi1;
        } else b2 = fminf(b2, ob1);
        int row = r0 + tid;
        g_pd[cb * N_ROWS + row] = b1;
        g_ps[cb * N_ROWS + row] = b2;
        g_pi[cb * N_ROWS + row] = i1;
    }
}

// ---------------------------------------------------------------------------
// post: pick + candidate refine + full-scan rescue + gather + loss partial.
// ---------------------------------------------------------------------------
__global__ void __launch_bounds__(256)
k_post(const float* __restrict__ z_e, const float* __restrict__ emb,
       float* __restrict__ res, float* __restrict__ out_idx_f)
{
    extern __shared__ float esm[];           // 128 x 257
    __shared__ int   idx_sm[128];
    __shared__ int   full_list[128];
    __shared__ int   ref_list[128];
    __shared__ int   cand[128][8];
    __shared__ int   ccnt[128];
    __shared__ int   nfull_s, nref_s;
    __shared__ float zrow[256];
    __shared__ float wd[8]; __shared__ int wk[8];
    __shared__ float wsum[8];

    const int tid = threadIdx.x;
    const int wid = tid >> 5, lane = tid & 31;
    const int r0 = blockIdx.x * 128;
    const int b = r0 >> 10, hw0 = r0 & 1023;

    if (tid == 0) { nfull_s = 0; nref_s = 0; }
    __syncthreads();

    // classify
    if (tid < 128) {
        int row = r0 + tid;
        float V1 = FLT_MAX; int bi = 0x7fffffff;
        float v1[8], v2[8]; int i1[8];
        #pragma unroll
        for (int cb = 0; cb < NCB; cb++) {
            v1[cb] = g_pd[cb * N_ROWS + row];
            v2[cb] = g_ps[cb * N_ROWS + row];
            i1[cb] = g_pi[cb * N_ROWS + row];
            if (v1[cb] < V1 || (v1[cb] == V1 && i1[cb] < bi)) { V1 = v1[cb]; bi = i1[cb]; }
        }
        idx_sm[tid] = bi;
        float th = V1 + E2;
        bool unc = false; int nc = 0; int cl[8];
        #pragma unroll
        for (int cb = 0; cb < NCB; cb++) {
            if (v2[cb] < th) unc = true;
            if (v1[cb] < th) cl[nc++] = i1[cb];
        }
        if (unc) {
            full_list[atomicAdd(&nfull_s, 1)] = tid;
        } else if (nc > 1) {
            int p = atomicAdd(&nref_s, 1);
            ref_list[p] = tid;
            ccnt[tid] = nc;
            #pragma unroll
            for (int q = 0; q < 8; q++) if (q < nc) cand[tid][q] = cl[q];
        }
    }
    __syncthreads();

    // candidate refine: warp per entry, exact fp32
    for (int j = wid; j < nref_s; j += 8) {
        int rl = ref_list[j];
        int hw = hw0 + rl;
        float zreg[8];
        #pragma unroll
        for (int cc = 0; cc < 8; cc++)
            zreg[cc] = z_e[(((size_t)(b * C_DIM + cc * 32 + lane)) << 10) + hw];
        int nc = ccnt[rl];
        float bd = FLT_MAX; int bk = 0x7fffffff;
        for (int ci = 0; ci < nc; ci++) {
            int k = cand[rl][ci];
            const float* er = emb + (size_t)k * C_DIM;
            float acc = 0.0f;
            #pragma unroll
            for (int cc = 0; cc < 8; cc++)
                acc += zreg[cc] * er[cc * 32 + lane];
            #pragma unroll
            for (int m = 16; m; m >>= 1) acc += __shfl_xor_sync(0xffffffffu, acc, m);
            float dd = g_enorm[k] - 2.0f * acc;
            if (dd < bd || (dd == bd && k < bk)) { bd = dd; bk = k; }
        }
        if (lane == 0) idx_sm[rl] = bk;
    }

    // full-scan rescue: block-cooperative, coalesced via embT
    int nfull = nfull_s;
    for (int j = 0; j < nfull; j++) {
        int rl = full_list[j];
        __syncthreads();
        zrow[tid] = z_e[(((size_t)(b * C_DIM + tid)) << 10) + hw0 + rl];
        __syncthreads();
        float bd = FLT_MAX; int bk = 0x7fffffff;
        #pragma unroll
        for (int gch = 0; gch < 4; gch++) {
            int k = wid * 128 + gch * 32 + lane;
            float acc = 0.0f;
            #pragma unroll 8
            for (int c = 0; c < C_DIM; c++)
                acc = fmaf(zrow[c], embT[c * K_CODES + k], acc);
            float dd = g_enorm[k] + acc;
            if (dd < bd) { bd = dd; bk = k; }   // k increasing -> ties keep lower k
        }
        #pragma unroll
        for (int m = 16; m; m >>= 1) {
            float obd = __shfl_xor_sync(0xffffffffu, bd, m);
            int   obk = __shfl_xor_sync(0xffffffffu, bk, m);
            if (obd < bd || (obd == bd && obk < bk)) { bd = obd; bk = obk; }
        }
        if (lane == 0) { wd[wid] = bd; wk[wid] = bk; }
        __syncthreads();
        if (tid == 0) {
            float B = FLT_MAX; int K = 0x7fffffff;
            #pragma unroll
            for (int w = 0; w < 8; w++)
                if (wd[w] < B || (wd[w] == B && wk[w] < K)) { B = wd[w]; K = wk[w]; }
            idx_sm[rl] = K;
        }
    }
    __syncthreads();

    if (tid < 128) out_idx_f[r0 + tid] = (float)idx_sm[tid];

    // gather + loss partial
    for (int i = tid; i < 128 * 256; i += 256) {
        int r = i >> 8, c = i & 255;
        esm[r * 257 + c] = emb[idx_sm[r] * C_DIM + c];
    }
    __syncthreads();

    float acc = 0.0f;
    const int r = tid & 127, chalf = tid >> 7;
    for (int cc = 0; cc < 256; cc += 2) {
        int c = cc + chalf;
        float v = esm[r * 257 + c];
        size_t gi = (((size_t)(b * C_DIM + c)) << 10) + hw0 + r;
        float zv = z_e[gi];
        res[gi] = v;
        float df = v - zv;
        acc += df * df;
    }
    #pragma unroll
    for (int m = 16; m; m >>= 1) acc += __shfl_xor_sync(0xffffffffu, acc, m);
    if (lane == 0) wsum[wid] = acc;
    __syncthreads();
    if (tid == 0) {
        float s = 0.0f;
        #pragma unroll
        for (int w = 0; w < 8; w++) s += wsum[w];
        g_partial[blockIdx.x] = s;
    }
}

__global__ void k_loss(float* __restrict__ out_loss) {
    __shared__ float s[256];
    int tid = threadIdx.x;
    s[tid] = g_partial[tid];
    __syncthreads();
    for (int st = 128; st > 0; st >>= 1) {
        if (tid < st) s[tid] += s[tid + st];
        __syncthreads();
    }
    if (tid == 0) out_loss[0] = 1.25f * (s[0] / 8388608.0f);
}

// ---------------------------------------------------------------------------
extern "C" void kernel_launch(void* const* d_in, const int* in_sizes, int n_in,
                              void* d_out, int out_size)
{
    const float* z_e = (const float*)d_in[0];
    const float* emb = (const float*)d_in[1];

    float* out  = (float*)d_out;
    float* res  = out;
    float* loss = out + 8388608;
    float* idxf = out + 8388609;

    cudaFuncSetAttribute(k_mma,  cudaFuncAttributeMaxDynamicSharedMemorySize, SMEM_MMA);
    cudaFuncSetAttribute(k_post, cudaFuncAttributeMaxDynamicSharedMemorySize, SMEM_POST);

    k_prep <<<128, 256>>>(emb);
    k_mma  <<<dim3(NCB, N_ROWS / 128), 256, SMEM_MMA>>>(z_e);
    k_post <<<N_ROWS / 128, 256, SMEM_POST>>>(z_e, emb, res, idxf);
    k_loss <<<1, 256>>>(loss);
}

// round 12
// speedup vs baseline: 1.2166x; 1.0009x over previous
#include <cuda_runtime.h>
#include <cstdint>
#include <cfloat>

typedef unsigned int u32;

#define N_ROWS  32768
#define C_DIM   256
#define K_CODES 1024
#define NCB     8          // code-blocks of 128
#define NCHUNK  8          // chunks of 32 c (K logical = 256, hi*hi only)
#define E2      0.5f       // 2*E; validated R7/R8/R10/R11
#define NSTAGE  3
#define A_STRIDE 136       // = 8 mod 32 banks -> frag bank = 8*(lane&3)+(lane>>2): bijective
#define A_FLOATS (32 * A_STRIDE)          // 4352
#define A_BYTES  (A_FLOATS * 4)           // 17408
#define STAGE_BYTES (A_BYTES + 16384)     // 33792
#define SMEM_MMA (NSTAGE * STAGE_BYTES)   // 101376 -> 2 CTAs/SM
#define SMEM_POST (128 * 257 * 4)

// efr: [code_tile(128)][kt(32)][lane 32][reg 2]  (tf32 hi of -2*emb)
__device__ float efr[(size_t)(K_CODES / 8) * 32 * 64];
__device__ float embT[C_DIM * K_CODES];    // [c][k] = -2*emb[k][c], exact fp32
__device__ float g_enorm[K_CODES];
__device__ float g_pd[NCB * N_ROWS];
__device__ float g_ps[NCB * N_ROWS];
__device__ int   g_pi[NCB * N_ROWS];
__device__ float g_partial[256];
__device__ int   g_done;

// ---------------- helpers ----------------
__device__ __forceinline__ u32 smem_u32(const void* p) {
    return (u32)__cvta_generic_to_shared(p);
}
__device__ __forceinline__ void cp16(u32 dst, const void* src) {
    asm volatile("cp.async.cg.shared.global [%0], [%1], 16;" :: "r"(dst), "l"(src));
}
__device__ __forceinline__ u32 tf32u(float v) {
    u32 r; asm("cvt.rna.satfinite.tf32.f32 %0, %1;" : "=r"(r) : "f"(v));
    return r;
}
__device__ __forceinline__ void mma8(float* d, uint4 a, uint2 b) {
    asm("mma.sync.aligned.m16n8k8.row.col.f32.tf32.tf32.f32 "
        "{%0,%1,%2,%3}, {%4,%5,%6,%7}, {%8,%9}, {%0,%1,%2,%3};"
        : "+f"(d[0]), "+f"(d[1]), "+f"(d[2]), "+f"(d[3])
        : "r"(a.x), "r"(a.y), "r"(a.z), "r"(a.w), "r"(b.x), "r"(b.y));
}
__device__ __forceinline__ void upd(float& b1, float& b2, int& i1, float v, int k) {
    if (v < b1 || (v == b1 && k < i1)) { b2 = b1; b1 = v; i1 = k; }
    else if (v < b2) b2 = v;
}

// ---------------------------------------------------------------------------
// prep (emb only): efr fragments + embT + norms. 128 blocks of 8 codes.
// Also resets g_done for the fused loss reduction (runs every replay).
// ---------------------------------------------------------------------------
__global__ void __launch_bounds__(256)
k_prep(const float* __restrict__ emb)
{
    const int tid = threadIdx.x;
    const int ct = blockIdx.x;        // code tile (8 codes)
    const int k0 = ct * 8;
    if (ct == 0 && tid == 0) g_done = 0;
    for (int j = tid; j < 2048; j += 256) {
        int within = j & 63, kt = j >> 6;
        int lane = within >> 1, reg = within & 1;
        int code = k0 + (lane >> 2);
        int cmod = kt * 8 + (lane & 3) + reg * 4;
        efr[(size_t)(ct * 32 + kt) * 64 + within] =
            __uint_as_float(tf32u(-2.0f * emb[code * C_DIM + cmod]));
    }
    for (int j = tid; j < 2048; j += 256) {
        int c = j >> 3, kk = j & 7;
        embT[c * K_CODES + k0 + kk] = -2.0f * emb[(k0 + kk) * C_DIM + c];
    }
    int wid = tid >> 5, lane = tid & 31;
    int code = k0 + wid;
    const float4* p = (const float4*)(emb + code * C_DIM);
    float4 a = p[lane];
    float4 b = p[lane + 32];
    float s = a.x*a.x + a.y*a.y + a.z*a.z + a.w*a.w
            + b.x*b.x + b.y*b.y + b.z*b.z + b.w*b.w;
    #pragma unroll
    for (int m = 16; m; m >>= 1) s += __shfl_xor_sync(0xffffffffu, s, m);
    if (lane == 0) g_enorm[code] = s;
}

// ---------------------------------------------------------------------------
// main: tf32 mma.sync GEMM (hi*hi) + argmin (best + second-best)
// CTA 128 rows x 128 codes, 8 warps (4 row x 2 col), warp tile 32x64.
// A direct from z_e (NCHW -> c-major smem, pad 136 = conflict-free frag reads),
// tf32 cvt in registers. B = efr fragments. 3-stage ring, 2 CTAs/SM.
// ---------------------------------------------------------------------------
__device__ __forceinline__ void load_chunk(u32 base, int buf, int ch,
                                           int b, int hw0, int cb, int tid,
                                           const float* __restrict__ z_e)
{
    u32 dst = base + (u32)buf * STAGE_BYTES;
    #pragma unroll
    for (int t2 = 0; t2 < 4; t2++) {           // A: 32 c x 128 rows, direct from z_e
        int t = tid + t2 * 256;
        int c = t >> 5, part = t & 31;
        cp16(dst + (u32)(c * (A_STRIDE * 4) + part * 16),
             z_e + (((size_t)(b * C_DIM + ch * 32 + c)) << 10) + hw0 + part * 4);
    }
    #pragma unroll
    for (int t2 = 0; t2 < 4; t2++) {           // B: 4kt x 16nt x 256B = 16KB
        int t = tid + t2 * 256;
        int tile = t >> 4, part = t & 15;
        int kt = tile >> 4, nt = tile & 15;
        cp16(dst + (u32)A_BYTES + (u32)((tile << 8) + (part << 4)),
             (const char*)efr + ((((size_t)(cb * 16 + nt) * 32 + ch * 4 + kt) << 8) + (part << 4)));
    }
    asm volatile("cp.async.commit_group;");
}

__global__ void __launch_bounds__(256, 2)
k_mma(const float* __restrict__ z_e)
{
    extern __shared__ float smf[];
    __shared__ float en_s[128];
    __shared__ float sd[2][128], ss[2][128];
    __shared__ int   si[2][128];

    const int tid = threadIdx.x;
    const int lane = tid & 31, wid = tid >> 5;
    const int warp_m = wid & 3, warp_n = wid >> 2;
    const int cb = blockIdx.x;             // fast dim -> L2 reuse of z_e
    const int rb = blockIdx.y;
    const int r0 = rb * 128;
    const int b = r0 >> 10, hw0 = r0 & 1023;
    const u32 base = smem_u32(smf);

    if (tid < 128) en_s[tid] = g_enorm[cb * 128 + tid];

    float d[2][8][4];
    #pragma unroll
    for (int m = 0; m < 2; m++)
        #pragma unroll
        for (int n = 0; n < 8; n++)
            #pragma unroll
            for (int q = 0; q < 4; q++) d[m][n][q] = 0.0f;

    load_chunk(base, 0, 0, b, hw0, cb, tid, z_e);
    load_chunk(base, 1, 1, b, hw0, cb, tid, z_e);

    const int frow = (lane >> 2);
    const int fc   = (lane & 3);

    for (int ch = 0; ch < NCHUNK; ch++) {
        int buf = ch % NSTAGE;
        if (ch < NCHUNK - 1) asm volatile("cp.async.wait_group 1;");
        else                 asm volatile("cp.async.wait_group 0;");
        __syncthreads();
        if (ch + 2 < NCHUNK) load_chunk(base, (ch + 2) % NSTAGE, ch + 2, b, hw0, cb, tid, z_e);

        const float* aS = smf + buf * (STAGE_BYTES / 4);
        const float* bS = aS + A_FLOATS;
        #pragma unroll
        for (int kt = 0; kt < 4; kt++) {
            uint4 a[2];
            uint2 bf[8];
            #pragma unroll
            for (int m = 0; m < 2; m++) {
                int rbase = warp_m * 32 + m * 16 + frow;
                int cbase = kt * 8 + fc;
                a[m].x = tf32u(aS[ cbase      * A_STRIDE + rbase    ]);
                a[m].y = tf32u(aS[ cbase      * A_STRIDE + rbase + 8]);
                a[m].z = tf32u(aS[(cbase + 4) * A_STRIDE + rbase    ]);
                a[m].w = tf32u(aS[(cbase + 4) * A_STRIDE + rbase + 8]);
            }
            #pragma unroll
            for (int n = 0; n < 8; n++)
                bf[n] = *(const uint2*)(bS + (((kt * 16 + warp_n * 8 + n) << 6) + (lane << 1)));
            #pragma unroll
            for (int m = 0; m < 2; m++)
                #pragma unroll
                for (int n = 0; n < 8; n++)
                    mma8(d[m][n], a[m], bf[n]);
        }
    }

    // epilogue: dist = acc + ||e||^2 ; best + second-best per row
    const int g = lane >> 2, tq = lane & 3;
    const int wm0 = warp_m * 32, wn0 = warp_n * 64;
    #pragma unroll
    for (int m = 0; m < 2; m++) {
        #pragma unroll
        for (int h = 0; h < 2; h++) {
            float b1 = FLT_MAX, b2 = FLT_MAX; int i1 = 0x7fffffff;
            #pragma unroll
            for (int n = 0; n < 8; n++) {
                int cl = wn0 + n * 8 + 2 * tq;
                float v0 = d[m][n][2 * h]     + en_s[cl];
                float v1 = d[m][n][2 * h + 1] + en_s[cl + 1];
                int k0 = cb * 128 + cl;
                upd(b1, b2, i1, v0, k0);
                upd(b1, b2, i1, v1, k0 + 1);
            }
            #pragma unroll
            for (int s = 1; s <= 2; s <<= 1) {
                float ob1 = __shfl_xor_sync(0xffffffffu, b1, s);
                float ob2 = __shfl_xor_sync(0xffffffffu, b2, s);
                int   oi1 = __shfl_xor_sync(0xffffffffu, i1, s);
                if (ob1 < b1 || (ob1 == b1 && oi1 < i1)) {
                    b2 = fminf(b1, ob2); b1 = ob1; i1 = oi1;
                } else b2 = fminf(b2, ob1);
            }
            if (tq == 0) {
                int rl = wm0 + m * 16 + h * 8 + g;
                sd[warp_n][rl] = b1; ss[warp_n][rl] = b2; si[warp_n][rl] = i1;
            }
        }
    }
    __syncthreads();
    if (tid < 128) {
        float b1 = sd[0][tid], b2 = ss[0][tid]; int i1 = si[0][tid];
        float ob1 = sd[1][tid], ob2 = ss[1][tid]; int oi1 = si[1][tid];
        if (ob1 < b1 || (ob1 == b1 && oi1 < i1)) {
            b2 = fminf(b1, ob2); b1 = ob1; i1 = oi1;
        } else b2 = fminf(b2, ob1);
        int row = r0 + tid;
        g_pd[cb * N_ROWS + row] = b1;
        g_ps[cb * N_ROWS + row] = b2;
        g_pi[cb * N_ROWS + row] = i1;
    }
}

// ---------------------------------------------------------------------------
// post: pick + candidate refine + full-scan rescue + gather + loss (fused).
// ---------------------------------------------------------------------------
__global__ void __launch_bounds__(256)
k_post(const float* __restrict__ z_e, const float* __restrict__ emb,
       float* __restrict__ res, float* __restrict__ out_idx_f,
       float* __restrict__ out_loss)
{
    extern __shared__ float esm[];           // 128 x 257
    __shared__ int   idx_sm[128];
    __shared__ int   full_list[128];
    __shared__ int   ref_list[128];
    __shared__ int   cand[128][8];
    __shared__ int   ccnt[128];
    __shared__ int   nfull_s, nref_s;
    __shared__ float zrow[256];
    __shared__ float wd[8]; __shared__ int wk[8];
    __shared__ float wsum[8];
    __shared__ int   lastflag;

    const int tid = threadIdx.x;
    const int wid = tid >> 5, lane = tid & 31;
    const int r0 = blockIdx.x * 128;
    const int b = r0 >> 10, hw0 = r0 & 1023;

    if (tid == 0) { nfull_s = 0; nref_s = 0; }
    __syncthreads();

    // classify
    if (tid < 128) {
        int row = r0 + tid;
        float V1 = FLT_MAX; int bi = 0x7fffffff;
        float v1[8], v2[8]; int i1[8];
        #pragma unroll
        for (int cb = 0; cb < NCB; cb++) {
            v1[cb] = g_pd[cb * N_ROWS + row];
            v2[cb] = g_ps[cb * N_ROWS + row];
            i1[cb] = g_pi[cb * N_ROWS + row];
            if (v1[cb] < V1 || (v1[cb] == V1 && i1[cb] < bi)) { V1 = v1[cb]; bi = i1[cb]; }
        }
        idx_sm[tid] = bi;
        float th = V1 + E2;
        bool unc = false; int nc = 0; int cl[8];
        #pragma unroll
        for (int cb = 0; cb < NCB; cb++) {
            if (v2[cb] < th) unc = true;
            if (v1[cb] < th) cl[nc++] = i1[cb];
        }
        if (unc) {
            full_list[atomicAdd(&nfull_s, 1)] = tid;
        } else if (nc > 1) {
            int p = atomicAdd(&nref_s, 1);
            ref_list[p] = tid;
            ccnt[tid] = nc;
            #pragma unroll
            for (int q = 0; q < 8; q++) if (q < nc) cand[tid][q] = cl[q];
        }
    }
    __syncthreads();

    // candidate refine: warp per entry, exact fp32
    for (int j = wid; j < nref_s; j += 8) {
        int rl = ref_list[j];
        int hw = hw0 + rl;
        float zreg[8];
        #pragma unroll
        for (int cc = 0; cc < 8; cc++)
            zreg[cc] = z_e[(((size_t)(b * C_DIM + cc * 32 + lane)) << 10) + hw];
        int nc = ccnt[rl];
        float bd = FLT_MAX; int bk = 0x7fffffff;
        for (int ci = 0; ci < nc; ci++) {
            int k = cand[rl][ci];
            const float* er = emb + (size_t)k * C_DIM;
            float acc = 0.0f;
            #pragma unroll
            for (int cc = 0; cc < 8; cc++)
                acc += zreg[cc] * er[cc * 32 + lane];
            #pragma unroll
            for (int m = 16; m; m >>= 1) acc += __shfl_xor_sync(0xffffffffu, acc, m);
            float dd = g_enorm[k] - 2.0f * acc;
            if (dd < bd || (dd == bd && k < bk)) { bd = dd; bk = k; }
        }
        if (lane == 0) idx_sm[rl] = bk;
    }

    // full-scan rescue: block-cooperative, coalesced via embT
    int nfull = nfull_s;
    for (int j = 0; j < nfull; j++) {
        int rl = full_list[j];
        __syncthreads();
        zrow[tid] = z_e[(((size_t)(b * C_DIM + tid)) << 10) + hw0 + rl];
        __syncthreads();
        float bd = FLT_MAX; int bk = 0x7fffffff;
        #pragma unroll
        for (int gch = 0; gch < 4; gch++) {
            int k = wid * 128 + gch * 32 + lane;
            float acc = 0.0f;
            #pragma unroll 8
            for (int c = 0; c < C_DIM; c++)
                acc = fmaf(zrow[c], embT[c * K_CODES + k], acc);
            float dd = g_enorm[k] + acc;
            if (dd < bd) { bd = dd; bk = k; }   // k increasing -> ties keep lower k
        }
        #pragma unroll
        for (int m = 16; m; m >>= 1) {
            float obd = __shfl_xor_sync(0xffffffffu, bd, m);
            int   obk = __shfl_xor_sync(0xffffffffu, bk, m);
            if (obd < bd || (obd == bd && obk < bk)) { bd = obd; bk = obk; }
        }
        if (lane == 0) { wd[wid] = bd; wk[wid] = bk; }
        __syncthreads();
        if (tid == 0) {
            float B = FLT_MAX; int K = 0x7fffffff;
            #pragma unroll
            for (int w = 0; w < 8; w++)
                if (wd[w] < B || (wd[w] == B && wk[w] < K)) { B = wd[w]; K = wk[w]; }
            idx_sm[rl] = K;
        }
    }
    __syncthreads();

    if (tid < 128) out_idx_f[r0 + tid] = (float)idx_sm[tid];

    // gather + loss partial
    for (int i = tid; i < 128 * 256; i += 256) {
        int r = i >> 8, c = i & 255;
        esm[r * 257 + c] = emb[idx_sm[r] * C_DIM + c];
    }
    __syncthreads();

    float acc = 0.0f;
    const int r = tid & 127, chalf = tid >> 7;
    for (int cc = 0; cc < 256; cc += 2) {
        int c = cc + chalf;
        float v = esm[r * 257 + c];
        size_t gi = (((size_t)(b * C_DIM + c)) << 10) + hw0 + r;
        float zv = z_e[gi];
        res[gi] = v;
        float df = v - zv;
        acc += df * df;
    }
    #pragma unroll
    for (int m = 16; m; m >>= 1) acc += __shfl_xor_sync(0xffffffffu, acc, m);
    if (lane == 0) wsum[wid] = acc;
    __syncthreads();
    if (tid == 0) {
        float s = 0.0f;
        #pragma unroll
        for (int w = 0; w < 8; w++) s += wsum[w];
        g_partial[blockIdx.x] = s;
        __threadfence();
        lastflag = (atomicAdd(&g_done, 1) == 255) ? 1 : 0;
    }
    __syncthreads();
    if (lastflag && wid == 0) {
        __threadfence();
        float s = 0.0f;
        for (int j = lane; j < 256; j += 32) s += g_partial[j];
        #pragma unroll
        for (int m = 16; m; m >>= 1) s += __shfl_xor_sync(0xffffffffu, s, m);
        if (lane == 0) out_loss[0] = 1.25f * (s / 8388608.0f);
    }
}

// ---------------------------------------------------------------------------
extern "C" void kernel_launch(void* const* d_in, const int* in_sizes, int n_in,
                              void* d_out, int out_size)
{
    const float* z_e = (const float*)d_in[0];
    const float* emb = (const float*)d_in[1];

    float* out  = (float*)d_out;
    float* res  = out;
    float* loss = out + 8388608;
    float* idxf = out + 8388609;

    cudaFuncSetAttribute(k_mma,  cudaFuncAttributeMaxDynamicSharedMemorySize, SMEM_MMA);
    cudaFuncSetAttribute(k_post, cudaFuncAttributeMaxDynamicSharedMemorySize, SMEM_POST);

    k_prep <<<128, 256>>>(emb);
    k_mma  <<<dim3(NCB, N_ROWS / 128), 256, SMEM_MMA>>>(z_e);
    k_post <<<N_ROWS / 128, 256, SMEM_POST>>>(z_e, emb, res, idxf, loss);
}

// round 13
// speedup vs baseline: 1.2294x; 1.0105x over previous
#include <cuda_runtime.h>
#include <cstdint>
#include <cfloat>

typedef unsigned int u32;

#define N_ROWS  32768
#define C_DIM   256
#define K_CODES 1024
#define NCB     8          // code-blocks of 128
#define NCHUNK  8          // chunks of 32 c (K logical = 256, hi*hi only)
#define E2      0.5f       // 2*E; validated R7/R8/R10-R12
#define NSTAGE  3
#define A_STRIDE 136       // 8 mod 32 banks -> conflict-free frag reads
#define A_FLOATS (32 * A_STRIDE)          // 4352
#define A_BYTES  (A_FLOATS * 4)           // 17408
#define STAGE_BYTES (A_BYTES + 16384)     // 33792
#define SMEM_MMA (NSTAGE * STAGE_BYTES)   // 101376 -> 2 CTAs/SM
#define SMEM_POST (128 * 257 * 4)

// efr: [code_tile(128)][kt(32)][lane 32][reg 2]  (tf32 hi of -2*emb)
__device__ float efr[(size_t)(K_CODES / 8) * 32 * 64];
__device__ float embT[C_DIM * K_CODES];    // [c][k] = -2*emb[k][c], exact fp32
__device__ float g_enorm[K_CODES];
__device__ float g_pd[NCB * N_ROWS];
__device__ float g_ps[NCB * N_ROWS];
__device__ int   g_pi[NCB * N_ROWS];
__device__ float g_partial[256];           // per-post-block sum of chosen dist
__device__ float g_zsq[256];               // per-rowblock sum ||z||^2 (from k_mma cb==0)
__device__ int   g_done;

// ---------------- helpers ----------------
__device__ __forceinline__ u32 smem_u32(const void* p) {
    return (u32)__cvta_generic_to_shared(p);
}
__device__ __forceinline__ void cp16(u32 dst, const void* src) {
    asm volatile("cp.async.cg.shared.global [%0], [%1], 16;" :: "r"(dst), "l"(src));
}
__device__ __forceinline__ u32 tf32u(float v) {
    u32 r; asm("cvt.rna.satfinite.tf32.f32 %0, %1;" : "=r"(r) : "f"(v));
    return r;
}
__device__ __forceinline__ void mma8(float* d, uint4 a, uint2 b) {
    asm("mma.sync.aligned.m16n8k8.row.col.f32.tf32.tf32.f32 "
        "{%0,%1,%2,%3}, {%4,%5,%6,%7}, {%8,%9}, {%0,%1,%2,%3};"
        : "+f"(d[0]), "+f"(d[1]), "+f"(d[2]), "+f"(d[3])
        : "r"(a.x), "r"(a.y), "r"(a.z), "r"(a.w), "r"(b.x), "r"(b.y));
}
__device__ __forceinline__ void upd(float& b1, float& b2, int& i1, float v, int k) {
    if (v < b1 || (v == b1 && k < i1)) { b2 = b1; b1 = v; i1 = k; }
    else if (v < b2) b2 = v;
}

// ---------------------------------------------------------------------------
// zero: reset the loss-reduction counter (runs first every replay)
// ---------------------------------------------------------------------------
__global__ void k_zero() { if (threadIdx.x == 0) g_done = 0; }

// ---------------------------------------------------------------------------
// prep (emb only): efr fragments + embT + norms. 128 blocks of 8 codes.
// ---------------------------------------------------------------------------
__global__ void __launch_bounds__(256)
k_prep(const float* __restrict__ emb)
{
    const int tid = threadIdx.x;
    const int ct = blockIdx.x;        // code tile (8 codes)
    const int k0 = ct * 8;
    for (int j = tid; j < 2048; j += 256) {
        int within = j & 63, kt = j >> 6;
        int lane = within >> 1, reg = within & 1;
        int code = k0 + (lane >> 2);
        int cmod = kt * 8 + (lane & 3) + reg * 4;
        efr[(size_t)(ct * 32 + kt) * 64 + within] =
            __uint_as_float(tf32u(-2.0f * emb[code * C_DIM + cmod]));
    }
    for (int j = tid; j < 2048; j += 256) {
        int c = j >> 3, kk = j & 7;
        embT[c * K_CODES + k0 + kk] = -2.0f * emb[(k0 + kk) * C_DIM + c];
    }
    int wid = tid >> 5, lane = tid & 31;
    int code = k0 + wid;
    const float4* p = (const float4*)(emb + code * C_DIM);
    float4 a = p[lane];
    float4 b = p[lane + 32];
    float s = a.x*a.x + a.y*a.y + a.z*a.z + a.w*a.w
            + b.x*b.x + b.y*b.y + b.z*b.z + b.w*b.w;
    #pragma unroll
    for (int m = 16; m; m >>= 1) s += __shfl_xor_sync(0xffffffffu, s, m);
    if (lane == 0) g_enorm[code] = s;
}

// ---------------------------------------------------------------------------
// main: tf32 mma.sync GEMM (hi*hi) + argmin (best + second-best)
// CTA 128 rows x 128 codes, 8 warps (4 row x 2 col), warp tile 32x64.
// A direct from z_e; cb==0 CTAs also accumulate exact sum ||z||^2 per rowblock.
// ---------------------------------------------------------------------------
__device__ __forceinline__ void load_chunk(u32 base, int buf, int ch,
                                           int b, int hw0, int cb, int tid,
                                           const float* __restrict__ z_e)
{
    u32 dst = base + (u32)buf * STAGE_BYTES;
    #pragma unroll
    for (int t2 = 0; t2 < 4; t2++) {           // A: 32 c x 128 rows, direct from z_e
        int t = tid + t2 * 256;
        int c = t >> 5, part = t & 31;
        cp16(dst + (u32)(c * (A_STRIDE * 4) + part * 16),
             z_e + (((size_t)(b * C_DIM + ch * 32 + c)) << 10) + hw0 + part * 4);
    }
    #pragma unroll
    for (int t2 = 0; t2 < 4; t2++) {           // B: 4kt x 16nt x 256B = 16KB
        int t = tid + t2 * 256;
        int tile = t >> 4, part = t & 15;
        int kt = tile >> 4, nt = tile & 15;
        cp16(dst + (u32)A_BYTES + (u32)((tile << 8) + (part << 4)),
             (const char*)efr + ((((size_t)(cb * 16 + nt) * 32 + ch * 4 + kt) << 8) + (part << 4)));
    }
    asm volatile("cp.async.commit_group;");
}

__global__ void __launch_bounds__(256, 2)
k_mma(const float* __restrict__ z_e)
{
    extern __shared__ float smf[];
    __shared__ float en_s[128];
    __shared__ float sd[2][128], ss[2][128];
    __shared__ int   si[2][128];
    __shared__ float wsum2[8];

    const int tid = threadIdx.x;
    const int lane = tid & 31, wid = tid >> 5;
    const int warp_m = wid & 3, warp_n = wid >> 2;
    const int cb = blockIdx.x;             // fast dim -> L2 reuse of z_e
    const int rb = blockIdx.y;
    const int r0 = rb * 128;
    const int b = r0 >> 10, hw0 = r0 & 1023;
    const u32 base = smem_u32(smf);

    if (tid < 128) en_s[tid] = g_enorm[cb * 128 + tid];

    float d[2][8][4];
    #pragma unroll
    for (int m = 0; m < 2; m++)
        #pragma unroll
        for (int n = 0; n < 8; n++)
            #pragma unroll
            for (int q = 0; q < 4; q++) d[m][n][q] = 0.0f;

    load_chunk(base, 0, 0, b, hw0, cb, tid, z_e);
    load_chunk(base, 1, 1, b, hw0, cb, tid, z_e);

    const int frow = (lane >> 2);
    const int fc   = (lane & 3);
    float zsq = 0.0f;

    for (int ch = 0; ch < NCHUNK; ch++) {
        int buf = ch % NSTAGE;
        if (ch < NCHUNK - 1) asm volatile("cp.async.wait_group 1;");
        else                 asm volatile("cp.async.wait_group 0;");
        __syncthreads();
        if (ch + 2 < NCHUNK) load_chunk(base, (ch + 2) % NSTAGE, ch + 2, b, hw0, cb, tid, z_e);

        const float* aS = smf + buf * (STAGE_BYTES / 4);
        const float* bS = aS + A_FLOATS;

        if (cb == 0) {                     // exact sum ||z||^2 (1/8 of CTAs)
            #pragma unroll
            for (int t2 = 0; t2 < 16; t2++) {
                int j = tid + t2 * 256;    // 4096 values: c = j>>7, row = j&127
                float v = aS[(j >> 7) * A_STRIDE + (j & 127)];
                zsq = fmaf(v, v, zsq);
            }
        }

        #pragma unroll
        for (int kt = 0; kt < 4; kt++) {
            uint4 a[2];
            uint2 bf[8];
            #pragma unroll
            for (int m = 0; m < 2; m++) {
                int rbase = warp_m * 32 + m * 16 + frow;
                int cbase = kt * 8 + fc;
                a[m].x = tf32u(aS[ cbase      * A_STRIDE + rbase    ]);
                a[m].y = tf32u(aS[ cbase      * A_STRIDE + rbase + 8]);
                a[m].z = tf32u(aS[(cbase + 4) * A_STRIDE + rbase    ]);
                a[m].w = tf32u(aS[(cbase + 4) * A_STRIDE + rbase + 8]);
            }
            #pragma unroll
            for (int n = 0; n < 8; n++)
                bf[n] = *(const uint2*)(bS + (((kt * 16 + warp_n * 8 + n) << 6) + (lane << 1)));
            #pragma unroll
            for (int m = 0; m < 2; m++)
                #pragma unroll
                for (int n = 0; n < 8; n++)
                    mma8(d[m][n], a[m], bf[n]);
        }
    }

    // epilogue: dist = acc + ||e||^2 ; best + second-best per row
    const int g = lane >> 2, tq = lane & 3;
    const int wm0 = warp_m * 32, wn0 = warp_n * 64;
    #pragma unroll
    for (int m = 0; m < 2; m++) {
        #pragma unroll
        for (int h = 0; h < 2; h++) {
            float b1 = FLT_MAX, b2 = FLT_MAX; int i1 = 0x7fffffff;
            #pragma unroll
            for (int n = 0; n < 8; n++) {
                int cl = wn0 + n * 8 + 2 * tq;
                float v0 = d[m][n][2 * h]     + en_s[cl];
                float v1 = d[m][n][2 * h + 1] + en_s[cl + 1];
                int k0 = cb * 128 + cl;
                upd(b1, b2, i1, v0, k0);
                upd(b1, b2, i1, v1, k0 + 1);
            }
            #pragma unroll
            for (int s = 1; s <= 2; s <<= 1) {
                float ob1 = __shfl_xor_sync(0xffffffffu, b1, s);
                float ob2 = __shfl_xor_sync(0xffffffffu, b2, s);
                int   oi1 = __shfl_xor_sync(0xffffffffu, i1, s);
                if (ob1 < b1 || (ob1 == b1 && oi1 < i1)) {
                    b2 = fminf(b1, ob2); b1 = ob1; i1 = oi1;
                } else b2 = fminf(b2, ob1);
            }
            if (tq == 0) {
                int rl = wm0 + m * 16 + h * 8 + g;
                sd[warp_n][rl] = b1; ss[warp_n][rl] = b2; si[warp_n][rl] = i1;
            }
        }
    }

    if (cb == 0) {                          // reduce zsq (deterministic order)
        #pragma unroll
        for (int m = 16; m; m >>= 1) zsq += __shfl_xor_sync(0xffffffffu, zsq, m);
        if (lane == 0) wsum2[wid] = zsq;
    }
    __syncthreads();
    if (tid < 128) {
        float b1 = sd[0][tid], b2 = ss[0][tid]; int i1 = si[0][tid];
        float ob1 = sd[1][tid], ob2 = ss[1][tid]; int oi1 = si[1][tid];
        if (ob1 < b1 || (ob1 == b1 && oi1 < i1)) {
            b2 = fminf(b1, ob2); b1 = ob1; i1 = oi1;
        } else b2 = fminf(b2, ob1);
        int row = r0 + tid;
        g_pd[cb * N_ROWS + row] = b1;
        g_ps[cb * N_ROWS + row] = b2;
        g_pi[cb * N_ROWS + row] = i1;
    }
    if (cb == 0 && tid == 0) {
        float s = 0.0f;
        #pragma unroll
        for (int w = 0; w < 8; w++) s += wsum2[w];
        g_zsq[rb] = s;
    }
}

// ---------------------------------------------------------------------------
// post: pick + candidate refine + full-scan rescue + gather/res + fused loss.
// Loss uses sum ||z||^2 (exact, from k_mma) + chosen distances
// (exact for refined/rescued rows, tf32-approx for clear winners: bias < 1e-4 rel).
// ---------------------------------------------------------------------------
__global__ void __launch_bounds__(256)
k_post(const float* __restrict__ z_e, const float* __restrict__ emb,
       float* __restrict__ res, float* __restrict__ out_idx_f,
       float* __restrict__ out_loss)
{
    extern __shared__ float esm[];           // 128 x 257
    __shared__ int   idx_sm[128];
    __shared__ float dist_sm[128];
    __shared__ int   full_list[128];
    __shared__ int   ref_list[128];
    __shared__ int   cand[128][8];
    __shared__ int   ccnt[128];
    __shared__ int   nfull_s, nref_s;
    __shared__ float zrow[256];
    __shared__ float wd[8]; __shared__ int wk[8];
    __shared__ float wsum[8];
    __shared__ int   lastflag;

    const int tid = threadIdx.x;
    const int wid = tid >> 5, lane = tid & 31;
    const int r0 = blockIdx.x * 128;
    const int b = r0 >> 10, hw0 = r0 & 1023;

    if (tid == 0) { nfull_s = 0; nref_s = 0; }
    __syncthreads();

    // classify
    if (tid < 128) {
        int row = r0 + tid;
        float V1 = FLT_MAX; int bi = 0x7fffffff;
        float v1[8], v2[8]; int i1[8];
        #pragma unroll
        for (int cb = 0; cb < NCB; cb++) {
            v1[cb] = g_pd[cb * N_ROWS + row];
            v2[cb] = g_ps[cb * N_ROWS + row];
            i1[cb] = g_pi[cb * N_ROWS + row];
            if (v1[cb] < V1 || (v1[cb] == V1 && i1[cb] < bi)) { V1 = v1[cb]; bi = i1[cb]; }
        }
        idx_sm[tid] = bi;
        dist_sm[tid] = V1;
        float th = V1 + E2;
        bool unc = false; int nc = 0; int cl[8];
        #pragma unroll
        for (int cb = 0; cb < NCB; cb++) {
            if (v2[cb] < th) unc = true;
            if (v1[cb] < th) cl[nc++] = i1[cb];
        }
        if (unc) {
            full_list[atomicAdd(&nfull_s, 1)] = tid;
        } else if (nc > 1) {
            int p = atomicAdd(&nref_s, 1);
            ref_list[p] = tid;
            ccnt[tid] = nc;
            #pragma unroll
            for (int q = 0; q < 8; q++) if (q < nc) cand[tid][q] = cl[q];
        }
    }
    __syncthreads();

    // candidate refine: warp per entry, exact fp32 (also yields exact dist)
    for (int j = wid; j < nref_s; j += 8) {
        int rl = ref_list[j];
        int hw = hw0 + rl;
        float zreg[8];
        #pragma unroll
        for (int cc = 0; cc < 8; cc++)
            zreg[cc] = z_e[(((size_t)(b * C_DIM + cc * 32 + lane)) << 10) + hw];
        int nc = ccnt[rl];
        float bd = FLT_MAX; int bk = 0x7fffffff;
        for (int ci = 0; ci < nc; ci++) {
            int k = cand[rl][ci];
            const float* er = emb + (size_t)k * C_DIM;
            float acc = 0.0f;
            #pragma unroll
            for (int cc = 0; cc < 8; cc++)
                acc += zreg[cc] * er[cc * 32 + lane];
            #pragma unroll
            for (int m = 16; m; m >>= 1) acc += __shfl_xor_sync(0xffffffffu, acc, m);
            float dd = g_enorm[k] - 2.0f * acc;
            if (dd < bd || (dd == bd && k < bk)) { bd = dd; bk = k; }
        }
        if (lane == 0) { idx_sm[rl] = bk; dist_sm[rl] = bd; }
    }

    // full-scan rescue: block-cooperative, coalesced via embT (exact dist)
    int nfull = nfull_s;
    for (int j = 0; j < nfull; j++) {
        int rl = full_list[j];
        __syncthreads();
        zrow[tid] = z_e[(((size_t)(b * C_DIM + tid)) << 10) + hw0 + rl];
        __syncthreads();
        float bd = FLT_MAX; int bk = 0x7fffffff;
        #pragma unroll
        for (int gch = 0; gch < 4; gch++) {
            int k = wid * 128 + gch * 32 + lane;
            float acc = 0.0f;
            #pragma unroll 8
            for (int c = 0; c < C_DIM; c++)
                acc = fmaf(zrow[c], embT[c * K_CODES + k], acc);
            float dd = g_enorm[k] + acc;
            if (dd < bd) { bd = dd; bk = k; }   // k increasing -> ties keep lower k
        }
        #pragma unroll
        for (int m = 16; m; m >>= 1) {
            float obd = __shfl_xor_sync(0xffffffffu, bd, m);
            int   obk = __shfl_xor_sync(0xffffffffu, bk, m);
            if (obd < bd || (obd == bd && obk < bk)) { bd = obd; bk = obk; }
        }
        if (lane == 0) { wd[wid] = bd; wk[wid] = bk; }
        __syncthreads();
        if (tid == 0) {
            float B = FLT_MAX; int K = 0x7fffffff;
            #pragma unroll
            for (int w = 0; w < 8; w++)
                if (wd[w] < B || (wd[w] == B && wk[w] < K)) { B = wd[w]; K = wk[w]; }
            idx_sm[rl] = K;
            dist_sm[rl] = B;
        }
    }
    __syncthreads();

    if (tid < 128) out_idx_f[r0 + tid] = (float)idx_sm[tid];

    // gather + res write (no z pass)
    for (int i = tid; i < 128 * 256; i += 256) {
        int r = i >> 8, c = i & 255;
        esm[r * 257 + c] = emb[idx_sm[r] * C_DIM + c];
    }
    __syncthreads();
    {
        const int r = tid & 127, chalf = tid >> 7;
        for (int cc = 0; cc < 256; cc += 2) {
            int c = cc + chalf;
            res[(((size_t)(b * C_DIM + c)) << 10) + hw0 + r] = esm[r * 257 + c];
        }
    }

    // loss partial: sum of chosen distances over this block's rows
    float dv = (tid < 128) ? dist_sm[tid] : 0.0f;
    #pragma unroll
    for (int m = 16; m; m >>= 1) dv += __shfl_xor_sync(0xffffffffu, dv, m);
    if (lane == 0) wsum[wid] = dv;
    __syncthreads();
    if (tid == 0) {
        float s = 0.0f;
        #pragma unroll
        for (int w = 0; w < 8; w++) s += wsum[w];
        g_partial[blockIdx.x] = s;
        __threadfence();
        lastflag = (atomicAdd(&g_done, 1) == 255) ? 1 : 0;
    }
    __syncthreads();
    if (lastflag && wid == 0) {
        __threadfence();
        float s = 0.0f;
        for (int j = lane; j < 256; j += 32) s += g_partial[j] + g_zsq[j];
        #pragma unroll
        for (int m = 16; m; m >>= 1) s += __shfl_xor_sync(0xffffffffu, s, m);
        if (lane == 0) out_loss[0] = 1.25f * (s / 8388608.0f);
    }
}

// ---------------------------------------------------------------------------
extern "C" void kernel_launch(void* const* d_in, const int* in_sizes, int n_in,
                              void* d_out, int out_size)
{
    const float* z_e = (const float*)d_in[0];
    const float* emb = (const float*)d_in[1];

    float* out  = (float*)d_out;
    float* res  = out;
    float* loss = out + 8388608;
    float* idxf = out + 8388609;

    cudaFuncSetAttribute(k_mma,  cudaFuncAttributeMaxDynamicSharedMemorySize, SMEM_MMA);
    cudaFuncSetAttribute(k_post, cudaFuncAttributeMaxDynamicSharedMemorySize, SMEM_POST);

    k_zero <<<1, 32>>>();
    k_prep <<<128, 256>>>(emb);
    k_mma  <<<dim3(NCB, N_ROWS / 128), 256, SMEM_MMA>>>(z_e);
    k_post <<<N_ROWS / 128, 256, SMEM_POST>>>(z_e, emb, res, idxf, loss);
}

// round 14
// speedup vs baseline: 1.3358x; 1.0865x over previous
#include <cuda_runtime.h>
#include <cstdint>
#include <cfloat>

typedef unsigned int u32;

#define N_ROWS  32768
#define C_DIM   256
#define K_CODES 1024
#define NCB     8          // code-blocks of 128
#define NCHUNK  8          // chunks of 32 c (K logical = 256, hi*hi only)
#define E2      0.5f       // 2*E; validated R7-R13
#define NSTAGE  3
#define A_STRIDE 132       // (conflict padding proved immaterial in R12; keep smem small)
#define A_FLOATS (32 * A_STRIDE)          // 4224
#define A_BYTES  (A_FLOATS * 4)           // 16896
#define STAGE_BYTES (A_BYTES + 16384)     // 33280
#define SMEM_MMA (NSTAGE * STAGE_BYTES)   // 99840 -> 2 CTAs/SM
#define SMEM_POST (128 * 257 * 4)

// efr: [code_tile(128)][kt(32)][lane 32][reg 2]  (tf32 hi of -2*emb)
__device__ float efr[(size_t)(K_CODES / 8) * 32 * 64];
__device__ float embT[C_DIM * K_CODES];    // [c][k] = -2*emb[k][c], exact fp32
__device__ float g_enorm[K_CODES];
__device__ float4 g_tv4[NCB * N_ROWS];     // per (cb,row): top-4 approx dists (sorted)
__device__ int4   g_ti4[NCB * N_ROWS];     // matching code indices
__device__ float g_partial[256];           // per-post-block sum of chosen dist
__device__ float g_zsq[256];               // per-rowblock sum ||z||^2 (from k_mma cb==0)
__device__ int   g_done;

// ---------------- helpers ----------------
__device__ __forceinline__ u32 smem_u32(const void* p) {
    return (u32)__cvta_generic_to_shared(p);
}
__device__ __forceinline__ void cp16(u32 dst, const void* src) {
    asm volatile("cp.async.cg.shared.global [%0], [%1], 16;" :: "r"(dst), "l"(src));
}
__device__ __forceinline__ u32 tf32u(float v) {
    u32 r; asm("cvt.rna.satfinite.tf32.f32 %0, %1;" : "=r"(r) : "f"(v));
    return r;
}
__device__ __forceinline__ void mma8(float* d, uint4 a, uint2 b) {
    asm("mma.sync.aligned.m16n8k8.row.col.f32.tf32.tf32.f32 "
        "{%0,%1,%2,%3}, {%4,%5,%6,%7}, {%8,%9}, {%0,%1,%2,%3};"
        : "+f"(d[0]), "+f"(d[1]), "+f"(d[2]), "+f"(d[3])
        : "r"(a.x), "r"(a.y), "r"(a.z), "r"(a.w), "r"(b.x), "r"(b.y));
}
__device__ __forceinline__ bool lessp(float va, int ia, float vb, int ib) {
    return va < vb || (va == vb && ia < ib);
}
__device__ __forceinline__ void ins4(float v, int k, float* bv, int* bi) {
    if (lessp(v, k, bv[3], bi[3])) {
        bv[3] = v; bi[3] = k;
        if (lessp(bv[3], bi[3], bv[2], bi[2])) {
            float tv = bv[2]; bv[2] = bv[3]; bv[3] = tv;
            int ti = bi[2]; bi[2] = bi[3]; bi[3] = ti;
        }
        if (lessp(bv[2], bi[2], bv[1], bi[1])) {
            float tv = bv[1]; bv[1] = bv[2]; bv[2] = tv;
            int ti = bi[1]; bi[1] = bi[2]; bi[2] = ti;
        }
        if (lessp(bv[1], bi[1], bv[0], bi[0])) {
            float tv = bv[0]; bv[0] = bv[1]; bv[1] = tv;
            int ti = bi[0]; bi[0] = bi[1]; bi[1] = ti;
        }
    }
}
__device__ __forceinline__ void merge4_shfl(float* mv, int* mi, int delta) {
    float ov[4]; int oi[4];
    #pragma unroll
    for (int t = 0; t < 4; t++) {
        ov[t] = __shfl_xor_sync(0xffffffffu, mv[t], delta);
        oi[t] = __shfl_xor_sync(0xffffffffu, mi[t], delta);
    }
    float rv[4]; int ri[4]; int a = 0, b = 0;
    #pragma unroll
    for (int t = 0; t < 4; t++) {
        bool tm = lessp(mv[a], mi[a], ov[b], oi[b]);
        rv[t] = tm ? mv[a] : ov[b];
        ri[t] = tm ? mi[a] : oi[b];
        if (tm) a++; else b++;
    }
    #pragma unroll
    for (int t = 0; t < 4; t++) { mv[t] = rv[t]; mi[t] = ri[t]; }
}

// ---------------------------------------------------------------------------
// zero: reset the loss-reduction counter (runs first every replay)
// ---------------------------------------------------------------------------
__global__ void k_zero() { if (threadIdx.x == 0) g_done = 0; }

// ---------------------------------------------------------------------------
// prep (emb only): efr fragments + embT + norms. 128 blocks of 8 codes.
// ---------------------------------------------------------------------------
__global__ void __launch_bounds__(256)
k_prep(const float* __restrict__ emb)
{
    const int tid = threadIdx.x;
    const int ct = blockIdx.x;        // code tile (8 codes)
    const int k0 = ct * 8;
    for (int j = tid; j < 2048; j += 256) {
        int within = j & 63, kt = j >> 6;
        int lane = within >> 1, reg = within & 1;
        int code = k0 + (lane >> 2);
        int cmod = kt * 8 + (lane & 3) + reg * 4;
        efr[(size_t)(ct * 32 + kt) * 64 + within] =
            __uint_as_float(tf32u(-2.0f * emb[code * C_DIM + cmod]));
    }
    for (int j = tid; j < 2048; j += 256) {
        int c = j >> 3, kk = j & 7;
        embT[c * K_CODES + k0 + kk] = -2.0f * emb[(k0 + kk) * C_DIM + c];
    }
    int wid = tid >> 5, lane = tid & 31;
    int code = k0 + wid;
    const float4* p = (const float4*)(emb + code * C_DIM);
    float4 a = p[lane];
    float4 b = p[lane + 32];
    float s = a.x*a.x + a.y*a.y + a.z*a.z + a.w*a.w
            + b.x*b.x + b.y*b.y + b.z*b.z + b.w*b.w;
    #pragma unroll
    for (int m = 16; m; m >>= 1) s += __shfl_xor_sync(0xffffffffu, s, m);
    if (lane == 0) g_enorm[code] = s;
}

// ---------------------------------------------------------------------------
// main: tf32 mma.sync GEMM (hi*hi) + per-block TOP-4 argmin lists
// CTA 128 rows x 128 codes, 8 warps (4 row x 2 col), warp tile 32x64.
// ---------------------------------------------------------------------------
__device__ __forceinline__ void load_chunk(u32 base, int buf, int ch,
                                           int b, int hw0, int cb, int tid,
                                           const float* __restrict__ z_e)
{
    u32 dst = base + (u32)buf * STAGE_BYTES;
    #pragma unroll
    for (int t2 = 0; t2 < 4; t2++) {           // A: 32 c x 128 rows, direct from z_e
        int t = tid + t2 * 256;
        int c = t >> 5, part = t & 31;
        cp16(dst + (u32)(c * (A_STRIDE * 4) + part * 16),
             z_e + (((size_t)(b * C_DIM + ch * 32 + c)) << 10) + hw0 + part * 4);
    }
    #pragma unroll
    for (int t2 = 0; t2 < 4; t2++) {           // B: 4kt x 16nt x 256B = 16KB
        int t = tid + t2 * 256;
        int tile = t >> 4, part = t & 15;
        int kt = tile >> 4, nt = tile & 15;
        cp16(dst + (u32)A_BYTES + (u32)((tile << 8) + (part << 4)),
             (const char*)efr + ((((size_t)(cb * 16 + nt) * 32 + ch * 4 + kt) << 8) + (part << 4)));
    }
    asm volatile("cp.async.commit_group;");
}

__global__ void __launch_bounds__(256, 2)
k_mma(const float* __restrict__ z_e)
{
    extern __shared__ float smf[];
    __shared__ float en_s[128];
    __shared__ float sd4[2][128][4];
    __shared__ int   si4[2][128][4];
    __shared__ float wsum2[8];

    const int tid = threadIdx.x;
    const int lane = tid & 31, wid = tid >> 5;
    const int warp_m = wid & 3, warp_n = wid >> 2;
    const int cb = blockIdx.x;             // fast dim -> L2 reuse of z_e
    const int rb = blockIdx.y;
    const int r0 = rb * 128;
    const int b = r0 >> 10, hw0 = r0 & 1023;
    const u32 base = smem_u32(smf);

    if (tid < 128) en_s[tid] = g_enorm[cb * 128 + tid];

    float d[2][8][4];
    #pragma unroll
    for (int m = 0; m < 2; m++)
        #pragma unroll
        for (int n = 0; n < 8; n++)
            #pragma unroll
            for (int q = 0; q < 4; q++) d[m][n][q] = 0.0f;

    load_chunk(base, 0, 0, b, hw0, cb, tid, z_e);
    load_chunk(base, 1, 1, b, hw0, cb, tid, z_e);

    const int frow = (lane >> 2);
    const int fc   = (lane & 3);
    float zsq = 0.0f;

    for (int ch = 0; ch < NCHUNK; ch++) {
        int buf = ch % NSTAGE;
        if (ch < NCHUNK - 1) asm volatile("cp.async.wait_group 1;");
        else                 asm volatile("cp.async.wait_group 0;");
        __syncthreads();
        if (ch + 2 < NCHUNK) load_chunk(base, (ch + 2) % NSTAGE, ch + 2, b, hw0, cb, tid, z_e);

        const float* aS = smf + buf * (STAGE_BYTES / 4);
        const float* bS = aS + A_FLOATS;

        if (cb == 0) {                     // exact sum ||z||^2 (1/8 of CTAs)
            #pragma unroll
            for (int t2 = 0; t2 < 16; t2++) {
                int j = tid + t2 * 256;
                float v = aS[(j >> 7) * A_STRIDE + (j & 127)];
                zsq = fmaf(v, v, zsq);
            }
        }

        #pragma unroll
        for (int kt = 0; kt < 4; kt++) {
            uint4 a[2];
            uint2 bf[8];
            #pragma unroll
            for (int m = 0; m < 2; m++) {
                int rbase = warp_m * 32 + m * 16 + frow;
                int cbase = kt * 8 + fc;
                a[m].x = tf32u(aS[ cbase      * A_STRIDE + rbase    ]);
                a[m].y = tf32u(aS[ cbase      * A_STRIDE + rbase + 8]);
                a[m].z = tf32u(aS[(cbase + 4) * A_STRIDE + rbase    ]);
                a[m].w = tf32u(aS[(cbase + 4) * A_STRIDE + rbase + 8]);
            }
            #pragma unroll
            for (int n = 0; n < 8; n++)
                bf[n] = *(const uint2*)(bS + (((kt * 16 + warp_n * 8 + n) << 6) + (lane << 1)));
            #pragma unroll
            for (int m = 0; m < 2; m++)
                #pragma unroll
                for (int n = 0; n < 8; n++)
                    mma8(d[m][n], a[m], bf[n]);
        }
    }

    // epilogue: dist = acc + ||e||^2 ; per-row TOP-4 (sorted) per code-block
    const int g = lane >> 2, tq = lane & 3;
    const int wm0 = warp_m * 32, wn0 = warp_n * 64;
    #pragma unroll
    for (int m = 0; m < 2; m++) {
        #pragma unroll
        for (int h = 0; h < 2; h++) {
            float bv[4] = {FLT_MAX, FLT_MAX, FLT_MAX, FLT_MAX};
            int   bi_[4] = {0x7fffffff, 0x7fffffff, 0x7fffffff, 0x7fffffff};
            #pragma unroll
            for (int n = 0; n < 8; n++) {
                int cl = wn0 + n * 8 + 2 * tq;
                int k0 = cb * 128 + cl;
                ins4(d[m][n][2 * h]     + en_s[cl],     k0,     bv, bi_);
                ins4(d[m][n][2 * h + 1] + en_s[cl + 1], k0 + 1, bv, bi_);
            }
            merge4_shfl(bv, bi_, 1);
            merge4_shfl(bv, bi_, 2);
            if (tq == 0) {
                int rl = wm0 + m * 16 + h * 8 + g;
                #pragma unroll
                for (int t = 0; t < 4; t++) {
                    sd4[warp_n][rl][t] = bv[t];
                    si4[warp_n][rl][t] = bi_[t];
                }
            }
        }
    }

    if (cb == 0) {
        #pragma unroll
        for (int m = 16; m; m >>= 1) zsq += __shfl_xor_sync(0xffffffffu, zsq, m);
        if (lane == 0) wsum2[wid] = zsq;
    }
    __syncthreads();
    if (tid < 128) {
        float av[4], bvv[4]; int ai[4], bii[4];
        #pragma unroll
        for (int t = 0; t < 4; t++) {
            av[t] = sd4[0][tid][t]; ai[t] = si4[0][tid][t];
            bvv[t] = sd4[1][tid][t]; bii[t] = si4[1][tid][t];
        }
        float rv[4]; int ri[4]; int a = 0, bb = 0;
        #pragma unroll
        for (int t = 0; t < 4; t++) {
            bool tm = lessp(av[a], ai[a], bvv[bb], bii[bb]);
            rv[t] = tm ? av[a] : bvv[bb];
            ri[t] = tm ? ai[a] : bii[bb];
            if (tm) a++; else bb++;
        }
        size_t o = (size_t)cb * N_ROWS + r0 + tid;
        g_tv4[o] = make_float4(rv[0], rv[1], rv[2], rv[3]);
        g_ti4[o] = make_int4(ri[0], ri[1], ri[2], ri[3]);
    }
    if (cb == 0 && tid == 0) {
        float s = 0.0f;
        #pragma unroll
        for (int w = 0; w < 8; w++) s += wsum2[w];
        g_zsq[rb] = s;
    }
}

// ---------------------------------------------------------------------------
// post: pick + candidate refine (<=32 cands) + rare full rescue + gather/res
// + fused loss. Coverage: full scan only if some block's 4th-best < V1+E2.
// ---------------------------------------------------------------------------
__global__ void __launch_bounds__(256)
k_post(const float* __restrict__ z_e, const float* __restrict__ emb,
       float* __restrict__ res, float* __restrict__ out_idx_f,
       float* __restrict__ out_loss)
{
    extern __shared__ float esm[];           // 128 x 257
    __shared__ int   idx_sm[128];
    __shared__ float dist_sm[128];
    __shared__ int   full_list[128];
    __shared__ int   ref_list[128];
    __shared__ int   cand[128][32];
    __shared__ int   ccnt[128];
    __shared__ int   nfull_s, nref_s;
    __shared__ float zrow[256];
    __shared__ float wd[8]; __shared__ int wk[8];
    __shared__ float wsum[8];
    __shared__ int   lastflag;

    const int tid = threadIdx.x;
    const int wid = tid >> 5, lane = tid & 31;
    const int r0 = blockIdx.x * 128;
    const int b = r0 >> 10, hw0 = r0 & 1023;

    if (tid == 0) { nfull_s = 0; nref_s = 0; }
    __syncthreads();

    // classify using top-4 lists
    if (tid < 128) {
        int row = r0 + tid;
        float V1 = FLT_MAX; int bi = 0x7fffffff;
        float4 vv[NCB]; int4 kk[NCB];
        #pragma unroll
        for (int cb = 0; cb < NCB; cb++) {
            vv[cb] = g_tv4[(size_t)cb * N_ROWS + row];
            kk[cb] = g_ti4[(size_t)cb * N_ROWS + row];
            if (lessp(vv[cb].x, kk[cb].x, V1, bi)) { V1 = vv[cb].x; bi = kk[cb].x; }
        }
        idx_sm[tid] = bi;
        dist_sm[tid] = V1;
        float th = V1 + E2;
        bool unc = false; int nc = 0;
        #pragma unroll
        for (int cb = 0; cb < NCB; cb++) {
            if (vv[cb].w < th) unc = true;       // 4th-best too close: coverage risk
            if (vv[cb].x < th) cand[tid][nc++] = kk[cb].x;
            if (vv[cb].y < th) cand[tid][nc++] = kk[cb].y;
            if (vv[cb].z < th) cand[tid][nc++] = kk[cb].z;
            if (vv[cb].w < th) cand[tid][nc++] = kk[cb].w;
        }
        if (unc) {
            full_list[atomicAdd(&nfull_s, 1)] = tid;
        } else if (nc > 1) {
            int p = atomicAdd(&nref_s, 1);
            ref_list[p] = tid;
            ccnt[tid] = nc;
        }
    }
    __syncthreads();

    // candidate refine: warp per entry, exact fp32 (also yields exact dist)
    for (int j = wid; j < nref_s; j += 8) {
        int rl = ref_list[j];
        int hw = hw0 + rl;
        float zreg[8];
        #pragma unroll
        for (int cc = 0; cc < 8; cc++)
            zreg[cc] = z_e[(((size_t)(b * C_DIM + cc * 32 + lane)) << 10) + hw];
        int nc = ccnt[rl];
        float bd = FLT_MAX; int bk = 0x7fffffff;
        for (int ci = 0; ci < nc; ci++) {
            int k = cand[rl][ci];
            const float* er = emb + (size_t)k * C_DIM;
            float acc = 0.0f;
            #pragma unroll
            for (int cc = 0; cc < 8; cc++)
                acc += zreg[cc] * er[cc * 32 + lane];
            #pragma unroll
            for (int m = 16; m; m >>= 1) acc += __shfl_xor_sync(0xffffffffu, acc, m);
            float dd = g_enorm[k] - 2.0f * acc;
            if (dd < bd || (dd == bd && k < bk)) { bd = dd; bk = k; }
        }
        if (lane == 0) { idx_sm[rl] = bk; dist_sm[rl] = bd; }
    }

    // full-scan rescue (now rare): block-cooperative via embT
    int nfull = nfull_s;
    for (int j = 0; j < nfull; j++) {
        int rl = full_list[j];
        __syncthreads();
        zrow[tid] = z_e[(((size_t)(b * C_DIM + tid)) << 10) + hw0 + rl];
        __syncthreads();
        float bd = FLT_MAX; int bk = 0x7fffffff;
        #pragma unroll
        for (int gch = 0; gch < 4; gch++) {
            int k = wid * 128 + gch * 32 + lane;
            float acc = 0.0f;
            #pragma unroll 8
            for (int c = 0; c < C_DIM; c++)
                acc = fmaf(zrow[c], embT[c * K_CODES + k], acc);
            float dd = g_enorm[k] + acc;
            if (dd < bd) { bd = dd; bk = k; }   // k increasing -> ties keep lower k
        }
        #pragma unroll
        for (int m = 16; m; m >>= 1) {
            float obd = __shfl_xor_sync(0xffffffffu, bd, m);
            int   obk = __shfl_xor_sync(0xffffffffu, bk, m);
            if (obd < bd || (obd == bd && obk < bk)) { bd = obd; bk = obk; }
        }
        if (lane == 0) { wd[wid] = bd; wk[wid] = bk; }
        __syncthreads();
        if (tid == 0) {
            float B = FLT_MAX; int K = 0x7fffffff;
            #pragma unroll
            for (int w = 0; w < 8; w++)
                if (wd[w] < B || (wd[w] == B && wk[w] < K)) { B = wd[w]; K = wk[w]; }
            idx_sm[rl] = K;
            dist_sm[rl] = B;
        }
    }
    __syncthreads();

    if (tid < 128) out_idx_f[r0 + tid] = (float)idx_sm[tid];

    // gather + res write (no z pass)
    for (int i = tid; i < 128 * 256; i += 256) {
        int r = i >> 8, c = i & 255;
        esm[r * 257 + c] = emb[idx_sm[r] * C_DIM + c];
    }
    __syncthreads();
    {
        const int r = tid & 127, chalf = tid >> 7;
        for (int cc = 0; cc < 256; cc += 2) {
            int c = cc + chalf;
            res[(((size_t)(b * C_DIM + c)) << 10) + hw0 + r] = esm[r * 257 + c];
        }
    }

    // loss partial: sum of chosen distances over this block's rows
    float dv = (tid < 128) ? dist_sm[tid] : 0.0f;
    #pragma unroll
    for (int m = 16; m; m >>= 1) dv += __shfl_xor_sync(0xffffffffu, dv, m);
    if (lane == 0) wsum[wid] = dv;
    __syncthreads();
    if (tid == 0) {
        float s = 0.0f;
        #pragma unroll
        for (int w = 0; w < 8; w++) s += wsum[w];
        g_partial[blockIdx.x] = s;
        __threadfence();
        lastflag = (atomicAdd(&g_done, 1) == 255) ? 1 : 0;
    }
    __syncthreads();
    if (lastflag && wid == 0) {
        __threadfence();
        float s = 0.0f;
        for (int j = lane; j < 256; j += 32) s += g_partial[j] + g_zsq[j];
        #pragma unroll
        for (int m = 16; m; m >>= 1) s += __shfl_xor_sync(0xffffffffu, s, m);
        if (lane == 0) out_loss[0] = 1.25f * (s / 8388608.0f);
    }
}

// ---------------------------------------------------------------------------
extern "C" void kernel_launch(void* const* d_in, const int* in_sizes, int n_in,
                              void* d_out, int out_size)
{
    const float* z_e = (const float*)d_in[0];
    const float* emb = (const float*)d_in[1];

    float* out  = (float*)d_out;
    float* res  = out;
    float* loss = out + 8388608;
    float* idxf = out + 8388609;

    cudaFuncSetAttribute(k_mma,  cudaFuncAttributeMaxDynamicSharedMemorySize, SMEM_MMA);
    cudaFuncSetAttribute(k_post, cudaFuncAttributeMaxDynamicSharedMemorySize, SMEM_POST);

    k_zero <<<1, 32>>>();
    k_prep <<<128, 256>>>(emb);
    k_mma  <<<dim3(NCB, N_ROWS / 128), 256, SMEM_MMA>>>(z_e);
    k_post <<<N_ROWS / 128, 256, SMEM_POST>>>(z_e, emb, res, idxf, loss);
}

// round 15
// speedup vs baseline: 1.5658x; 1.1722x over previous
#include <cuda_runtime.h>
#include <cstdint>
#include <cfloat>

typedef unsigned int u32;

#define N_ROWS  32768
#define C_DIM   256
#define K_CODES 1024
#define NCB     8          // code-blocks of 128
#define NCHUNK  8          // chunks of 32 c (K logical = 256, hi*hi only)
#define E2      0.5f       // 2*E; validated R7-R14
#define NSTAGE  3
#define A_STRIDE 132
#define A_FLOATS (32 * A_STRIDE)          // 4224
#define A_BYTES  (A_FLOATS * 4)           // 16896
#define STAGE_BYTES (A_BYTES + 16384)     // 33280
#define SMEM_MMA (NSTAGE * STAGE_BYTES)   // 99840 -> 2 CTAs/SM
#define SMEM_POST (128 * 257 * 4)

// efr: [code_tile(128)][kt(32)][lane 32][reg 2]  (tf32 hi of -2*emb)
__device__ float efr[(size_t)(K_CODES / 8) * 32 * 64];
__device__ float embT[C_DIM * K_CODES];    // [c][k] = -2*emb[k][c], exact fp32
__device__ float g_enorm[K_CODES];
__device__ float4 g_tv4[NCB * N_ROWS];     // per (cb,row): top-4 approx dists (sorted)
__device__ int4   g_ti4[NCB * N_ROWS];     // matching code indices
__device__ float g_partial[256];           // per-post-block sum of chosen dist
__device__ float g_zsq[256];               // per-rowblock sum ||z||^2 (from k_mma cb==0)
__device__ int   g_done;

// ---------------- helpers ----------------
__device__ __forceinline__ u32 smem_u32(const void* p) {
    return (u32)__cvta_generic_to_shared(p);
}
__device__ __forceinline__ void cp16(u32 dst, const void* src) {
    asm volatile("cp.async.cg.shared.global [%0], [%1], 16;" :: "r"(dst), "l"(src));
}
__device__ __forceinline__ u32 tf32u(float v) {
    u32 r; asm("cvt.rna.satfinite.tf32.f32 %0, %1;" : "=r"(r) : "f"(v));
    return r;
}
__device__ __forceinline__ void mma8(float* d, uint4 a, uint2 b) {
    asm("mma.sync.aligned.m16n8k8.row.col.f32.tf32.tf32.f32 "
        "{%0,%1,%2,%3}, {%4,%5,%6,%7}, {%8,%9}, {%0,%1,%2,%3};"
        : "+f"(d[0]), "+f"(d[1]), "+f"(d[2]), "+f"(d[3])
        : "r"(a.x), "r"(a.y), "r"(a.z), "r"(a.w), "r"(b.x), "r"(b.y));
}
__device__ __forceinline__ bool lessp(float va, int ia, float vb, int ib) {
    return va < vb || (va == vb && ia < ib);
}
// constant-index sorted insert into bv[0..3] (ascending)
__device__ __forceinline__ void ins4(float v, int k, float* bv, int* bi) {
    if (lessp(v, k, bv[3], bi[3])) {
        bv[3] = v; bi[3] = k;
        if (lessp(bv[3], bi[3], bv[2], bi[2])) {
            float tv = bv[2]; bv[2] = bv[3]; bv[3] = tv;
            int ti = bi[2]; bi[2] = bi[3]; bi[3] = ti;
        }
        if (lessp(bv[2], bi[2], bv[1], bi[1])) {
            float tv = bv[1]; bv[1] = bv[2]; bv[2] = tv;
            int ti = bi[1]; bi[1] = bi[2]; bi[2] = ti;
        }
        if (lessp(bv[1], bi[1], bv[0], bi[0])) {
            float tv = bv[0]; bv[0] = bv[1]; bv[1] = tv;
            int ti = bi[0]; bi[0] = bi[1]; bi[1] = ti;
        }
    }
}
// branchless compare-swap (constant indices only at call sites)
__device__ __forceinline__ void cswap(float& va, int& ia, float& vb, int& ib) {
    bool sw = lessp(vb, ib, va, ia);
    float v0 = sw ? vb : va, v1 = sw ? va : vb;
    int   i0 = sw ? ib : ia, i1 = sw ? ia : ib;
    va = v0; vb = v1; ia = i0; ib = i1;
}
__device__ __forceinline__ void sort4_bitonic(float* w, int* wi) {
    cswap(w[0], wi[0], w[2], wi[2]);
    cswap(w[1], wi[1], w[3], wi[3]);
    cswap(w[0], wi[0], w[1], wi[1]);
    cswap(w[2], wi[2], w[3], wi[3]);
}
// merge this lane's sorted top-4 with XOR-partner lane's: min(a[t], b[3-t]) is
// the 4 smallest as a bitonic sequence; fixed network sorts it. No dyn indexing.
__device__ __forceinline__ void merge4_shfl(float* mv, int* mi, int delta) {
    float ov[4]; int oi[4];
    #pragma unroll
    for (int t = 0; t < 4; t++) {
        ov[t] = __shfl_xor_sync(0xffffffffu, mv[t], delta);
        oi[t] = __shfl_xor_sync(0xffffffffu, mi[t], delta);
    }
    float w[4]; int wi_[4];
    #pragma unroll
    for (int t = 0; t < 4; t++) {
        bool tm = lessp(mv[t], mi[t], ov[3 - t], oi[3 - t]);
        w[t]   = tm ? mv[t] : ov[3 - t];
        wi_[t] = tm ? mi[t] : oi[3 - t];
    }
    sort4_bitonic(w, wi_);
    #pragma unroll
    for (int t = 0; t < 4; t++) { mv[t] = w[t]; mi[t] = wi_[t]; }
}
// merge two sorted 4-lists in registers -> sorted top-4 (constant indices)
__device__ __forceinline__ void merge4_arrays(const float* av, const int* ai,
                                              const float* bv, const int* bi,
                                              float* rv, int* ri) {
    #pragma unroll
    for (int t = 0; t < 4; t++) {
        bool tm = lessp(av[t], ai[t], bv[3 - t], bi[3 - t]);
        rv[t] = tm ? av[t] : bv[3 - t];
        ri[t] = tm ? ai[t] : bi[3 - t];
    }
    sort4_bitonic(rv, ri);
}

// ---------------------------------------------------------------------------
// zero: reset the loss-reduction counter (runs first every replay)
// ---------------------------------------------------------------------------
__global__ void k_zero() { if (threadIdx.x == 0) g_done = 0; }

// ---------------------------------------------------------------------------
// prep (emb only): efr fragments + embT + norms. 128 blocks of 8 codes.
// ---------------------------------------------------------------------------
__global__ void __launch_bounds__(256)
k_prep(const float* __restrict__ emb)
{
    const int tid = threadIdx.x;
    const int ct = blockIdx.x;        // code tile (8 codes)
    const int k0 = ct * 8;
    for (int j = tid; j < 2048; j += 256) {
        int within = j & 63, kt = j >> 6;
        int lane = within >> 1, reg = within & 1;
        int code = k0 + (lane >> 2);
        int cmod = kt * 8 + (lane & 3) + reg * 4;
        efr[(size_t)(ct * 32 + kt) * 64 + within] =
            __uint_as_float(tf32u(-2.0f * emb[code * C_DIM + cmod]));
    }
    for (int j = tid; j < 2048; j += 256) {
        int c = j >> 3, kk = j & 7;
        embT[c * K_CODES + k0 + kk] = -2.0f * emb[(k0 + kk) * C_DIM + c];
    }
    int wid = tid >> 5, lane = tid & 31;
    int code = k0 + wid;
    const float4* p = (const float4*)(emb + code * C_DIM);
    float4 a = p[lane];
    float4 b = p[lane + 32];
    float s = a.x*a.x + a.y*a.y + a.z*a.z + a.w*a.w
            + b.x*b.x + b.y*b.y + b.z*b.z + b.w*b.w;
    #pragma unroll
    for (int m = 16; m; m >>= 1) s += __shfl_xor_sync(0xffffffffu, s, m);
    if (lane == 0) g_enorm[code] = s;
}

// ---------------------------------------------------------------------------
// main: tf32 mma.sync GEMM (hi*hi) + per-block TOP-4 argmin lists
// CTA 128 rows x 128 codes, 8 warps (4 row x 2 col), warp tile 32x64.
// ---------------------------------------------------------------------------
__device__ __forceinline__ void load_chunk(u32 base, int buf, int ch,
                                           int b, int hw0, int cb, int tid,
                                           const float* __restrict__ z_e)
{
    u32 dst = base + (u32)buf * STAGE_BYTES;
    #pragma unroll
    for (int t2 = 0; t2 < 4; t2++) {           // A: 32 c x 128 rows, direct from z_e
        int t = tid + t2 * 256;
        int c = t >> 5, part = t & 31;
        cp16(dst + (u32)(c * (A_STRIDE * 4) + part * 16),
             z_e + (((size_t)(b * C_DIM + ch * 32 + c)) << 10) + hw0 + part * 4);
    }
    #pragma unroll
    for (int t2 = 0; t2 < 4; t2++) {           // B: 4kt x 16nt x 256B = 16KB
        int t = tid + t2 * 256;
        int tile = t >> 4, part = t & 15;
        int kt = tile >> 4, nt = tile & 15;
        cp16(dst + (u32)A_BYTES + (u32)((tile << 8) + (part << 4)),
             (const char*)efr + ((((size_t)(cb * 16 + nt) * 32 + ch * 4 + kt) << 8) + (part << 4)));
    }
    asm volatile("cp.async.commit_group;");
}

__global__ void __launch_bounds__(256, 2)
k_mma(const float* __restrict__ z_e)
{
    extern __shared__ float smf[];
    __shared__ float en_s[128];
    __shared__ float sd4[2][128][4];
    __shared__ int   si4[2][128][4];
    __shared__ float wsum2[8];

    const int tid = threadIdx.x;
    const int lane = tid & 31, wid = tid >> 5;
    const int warp_m = wid & 3, warp_n = wid >> 2;
    const int cb = blockIdx.x;             // fast dim -> L2 reuse of z_e
    const int rb = blockIdx.y;
    const int r0 = rb * 128;
    const int b = r0 >> 10, hw0 = r0 & 1023;
    const u32 base = smem_u32(smf);

    if (tid < 128) en_s[tid] = g_enorm[cb * 128 + tid];

    float d[2][8][4];
    #pragma unroll
    for (int m = 0; m < 2; m++)
        #pragma unroll
        for (int n = 0; n < 8; n++)
            #pragma unroll
            for (int q = 0; q < 4; q++) d[m][n][q] = 0.0f;

    load_chunk(base, 0, 0, b, hw0, cb, tid, z_e);
    load_chunk(base, 1, 1, b, hw0, cb, tid, z_e);

    const int frow = (lane >> 2);
    const int fc   = (lane & 3);
    float zsq = 0.0f;

    for (int ch = 0; ch < NCHUNK; ch++) {
        int buf = ch % NSTAGE;
        if (ch < NCHUNK - 1) asm volatile("cp.async.wait_group 1;");
        else                 asm volatile("cp.async.wait_group 0;");
        __syncthreads();
        if (ch + 2 < NCHUNK) load_chunk(base, (ch + 2) % NSTAGE, ch + 2, b, hw0, cb, tid, z_e);

        const float* aS = smf + buf * (STAGE_BYTES / 4);
        const float* bS = aS + A_FLOATS;

        if (cb == 0) {                     // exact sum ||z||^2 (1/8 of CTAs)
            #pragma unroll
            for (int t2 = 0; t2 < 16; t2++) {
                int j = tid + t2 * 256;
                float v = aS[(j >> 7) * A_STRIDE + (j & 127)];
                zsq = fmaf(v, v, zsq);
            }
        }

        #pragma unroll
        for (int kt = 0; kt < 4; kt++) {
            uint4 a[2];
            uint2 bf[8];
            #pragma unroll
            for (int m = 0; m < 2; m++) {
                int rbase = warp_m * 32 + m * 16 + frow;
                int cbase = kt * 8 + fc;
                a[m].x = tf32u(aS[ cbase      * A_STRIDE + rbase    ]);
                a[m].y = tf32u(aS[ cbase      * A_STRIDE + rbase + 8]);
                a[m].z = tf32u(aS[(cbase + 4) * A_STRIDE + rbase    ]);
                a[m].w = tf32u(aS[(cbase + 4) * A_STRIDE + rbase + 8]);
            }
            #pragma unroll
            for (int n = 0; n < 8; n++)
                bf[n] = *(const uint2*)(bS + (((kt * 16 + warp_n * 8 + n) << 6) + (lane << 1)));
            #pragma unroll
            for (int m = 0; m < 2; m++)
                #pragma unroll
                for (int n = 0; n < 8; n++)
                    mma8(d[m][n], a[m], bf[n]);
        }
    }

    // epilogue: dist = acc + ||e||^2 ; per-row TOP-4 (sorted) per code-block
    const int g = lane >> 2, tq = lane & 3;
    const int wm0 = warp_m * 32, wn0 = warp_n * 64;
    #pragma unroll
    for (int m = 0; m < 2; m++) {
        #pragma unroll
        for (int h = 0; h < 2; h++) {
            float bv[4] = {FLT_MAX, FLT_MAX, FLT_MAX, FLT_MAX};
            int   bi_[4] = {0x7fffffff, 0x7fffffff, 0x7fffffff, 0x7fffffff};
            #pragma unroll
            for (int n = 0; n < 8; n++) {
                int cl = wn0 + n * 8 + 2 * tq;
                int k0 = cb * 128 + cl;
                ins4(d[m][n][2 * h]     + en_s[cl],     k0,     bv, bi_);
                ins4(d[m][n][2 * h + 1] + en_s[cl + 1], k0 + 1, bv, bi_);
            }
            merge4_shfl(bv, bi_, 1);
            merge4_shfl(bv, bi_, 2);
            if (tq == 0) {
                int rl = wm0 + m * 16 + h * 8 + g;
                #pragma unroll
                for (int t = 0; t < 4; t++) {
                    sd4[warp_n][rl][t] = bv[t];
                    si4[warp_n][rl][t] = bi_[t];
                }
            }
        }
    }

    if (cb == 0) {
        #pragma unroll
        for (int m = 16; m; m >>= 1) zsq += __shfl_xor_sync(0xffffffffu, zsq, m);
        if (lane == 0) wsum2[wid] = zsq;
    }
    __syncthreads();
    if (tid < 128) {
        float av[4], bvv[4], rv[4]; int ai[4], bii[4], ri[4];
        #pragma unroll
        for (int t = 0; t < 4; t++) {
            av[t] = sd4[0][tid][t]; ai[t] = si4[0][tid][t];
            bvv[t] = sd4[1][tid][t]; bii[t] = si4[1][tid][t];
        }
        merge4_arrays(av, ai, bvv, bii, rv, ri);
        size_t o = (size_t)cb * N_ROWS + r0 + tid;
        g_tv4[o] = make_float4(rv[0], rv[1], rv[2], rv[3]);
        g_ti4[o] = make_int4(ri[0], ri[1], ri[2], ri[3]);
    }
    if (cb == 0 && tid == 0) {
        float s = 0.0f;
        #pragma unroll
        for (int w = 0; w < 8; w++) s += wsum2[w];
        g_zsq[rb] = s;
    }
}

// ---------------------------------------------------------------------------
// post: pick + candidate refine (<=32 cands) + rare full rescue + gather/res
// + fused loss. Coverage: full scan only if some block's 4th-best < V1+E2.
// ---------------------------------------------------------------------------
__global__ void __launch_bounds__(256)
k_post(const float* __restrict__ z_e, const float* __restrict__ emb,
       float* __restrict__ res, float* __restrict__ out_idx_f,
       float* __restrict__ out_loss)
{
    extern __shared__ float esm[];           // 128 x 257
    __shared__ int   idx_sm[128];
    __shared__ float dist_sm[128];
    __shared__ int   full_list[128];
    __shared__ int   ref_list[128];
    __shared__ int   cand[128][32];
    __shared__ int   ccnt[128];
    __shared__ int   nfull_s, nref_s;
    __shared__ float zrow[256];
    __shared__ float wd[8]; __shared__ int wk[8];
    __shared__ float wsum[8];
    __shared__ int   lastflag;

    const int tid = threadIdx.x;
    const int wid = tid >> 5, lane = tid & 31;
    const int r0 = blockIdx.x * 128;
    const int b = r0 >> 10, hw0 = r0 & 1023;

    if (tid == 0) { nfull_s = 0; nref_s = 0; }
    __syncthreads();

    // classify using top-4 lists
    if (tid < 128) {
        int row = r0 + tid;
        float V1 = FLT_MAX; int bi = 0x7fffffff;
        float4 vv[NCB]; int4 kk[NCB];
        #pragma unroll
        for (int cb = 0; cb < NCB; cb++) {
            vv[cb] = g_tv4[(size_t)cb * N_ROWS + row];
            kk[cb] = g_ti4[(size_t)cb * N_ROWS + row];
            if (lessp(vv[cb].x, kk[cb].x, V1, bi)) { V1 = vv[cb].x; bi = kk[cb].x; }
        }
        idx_sm[tid] = bi;
        dist_sm[tid] = V1;
        float th = V1 + E2;
        bool unc = false; int nc = 0;
        #pragma unroll
        for (int cb = 0; cb < NCB; cb++) {
            if (vv[cb].w < th) unc = true;       // 4th-best too close: coverage risk
            if (vv[cb].x < th) cand[tid][nc++] = kk[cb].x;
            if (vv[cb].y < th) cand[tid][nc++] = kk[cb].y;
            if (vv[cb].z < th) cand[tid][nc++] = kk[cb].z;
            if (vv[cb].w < th) cand[tid][nc++] = kk[cb].w;
        }
        if (unc) {
            full_list[atomicAdd(&nfull_s, 1)] = tid;
        } else if (nc > 1) {
            int p = atomicAdd(&nref_s, 1);
            ref_list[p] = tid;
            ccnt[tid] = nc;
        }
    }
    __syncthreads();

    // candidate refine: warp per entry, exact fp32 (also yields exact dist)
    for (int j = wid; j < nref_s; j += 8) {
        int rl = ref_list[j];
        int hw = hw0 + rl;
        float zreg[8];
        #pragma unroll
        for (int cc = 0; cc < 8; cc++)
            zreg[cc] = z_e[(((size_t)(b * C_DIM + cc * 32 + lane)) << 10) + hw];
        int nc = ccnt[rl];
        float bd = FLT_MAX; int bk = 0x7fffffff;
        for (int ci = 0; ci < nc; ci++) {
            int k = cand[rl][ci];
            const float* er = emb + (size_t)k * C_DIM;
            float acc = 0.0f;
            #pragma unroll
            for (int cc = 0; cc < 8; cc++)
                acc += zreg[cc] * er[cc * 32 + lane];
            #pragma unroll
            for (int m = 16; m; m >>= 1) acc += __shfl_xor_sync(0xffffffffu, acc, m);
            float dd = g_enorm[k] - 2.0f * acc;
            if (dd < bd || (dd == bd && k < bk)) { bd = dd; bk = k; }
        }
        if (lane == 0) { idx_sm[rl] = bk; dist_sm[rl] = bd; }
    }

    // full-scan rescue (rare): block-cooperative via embT
    int nfull = nfull_s;
    for (int j = 0; j < nfull; j++) {
        int rl = full_list[j];
        __syncthreads();
        zrow[tid] = z_e[(((size_t)(b * C_DIM + tid)) << 10) + hw0 + rl];
        __syncthreads();
        float bd = FLT_MAX; int bk = 0x7fffffff;
        #pragma unroll
        for (int gch = 0; gch < 4; gch++) {
            int k = wid * 128 + gch * 32 + lane;
            float acc = 0.0f;
            #pragma unroll 8
            for (int c = 0; c < C_DIM; c++)
                acc = fmaf(zrow[c], embT[c * K_CODES + k], acc);
            float dd = g_enorm[k] + acc;
            if (dd < bd) { bd = dd; bk = k; }   // k increasing -> ties keep lower k
        }
        #pragma unroll
        for (int m = 16; m; m >>= 1) {
            float obd = __shfl_xor_sync(0xffffffffu, bd, m);
            int   obk = __shfl_xor_sync(0xffffffffu, bk, m);
            if (obd < bd || (obd == bd && obk < bk)) { bd = obd; bk = obk; }
        }
        if (lane == 0) { wd[wid] = bd; wk[wid] = bk; }
        __syncthreads();
        if (tid == 0) {
            float B = FLT_MAX; int K = 0x7fffffff;
            #pragma unroll
            for (int w = 0; w < 8; w++)
                if (wd[w] < B || (wd[w] == B && wk[w] < K)) { B = wd[w]; K = wk[w]; }
            idx_sm[rl] = K;
            dist_sm[rl] = B;
        }
    }
    __syncthreads();

    if (tid < 128) out_idx_f[r0 + tid] = (float)idx_sm[tid];

    // gather + res write (no z pass)
    for (int i = tid; i < 128 * 256; i += 256) {
        int r = i >> 8, c = i & 255;
        esm[r * 257 + c] = emb[idx_sm[r] * C_DIM + c];
    }
    __syncthreads();
    {
        const int r = tid & 127, chalf = tid >> 7;
        for (int cc = 0; cc < 256; cc += 2) {
            int c = cc + chalf;
            res[(((size_t)(b * C_DIM + c)) << 10) + hw0 + r] = esm[r * 257 + c];
        }
    }

    // loss partial: sum of chosen distances over this block's rows
    float dv = (tid < 128) ? dist_sm[tid] : 0.0f;
    #pragma unroll
    for (int m = 16; m; m >>= 1) dv += __shfl_xor_sync(0xffffffffu, dv, m);
    if (lane == 0) wsum[wid] = dv;
    __syncthreads();
    if (tid == 0) {
        float s = 0.0f;
        #pragma unroll
        for (int w = 0; w < 8; w++) s += wsum[w];
        g_partial[blockIdx.x] = s;
        __threadfence();
        lastflag = (atomicAdd(&g_done, 1) == 255) ? 1 : 0;
    }
    __syncthreads();
    if (lastflag && wid == 0) {
        __threadfence();
        float s = 0.0f;
        for (int j = lane; j < 256; j += 32) s += g_partial[j] + g_zsq[j];
        #pragma unroll
        for (int m = 16; m; m >>= 1) s += __shfl_xor_sync(0xffffffffu, s, m);
        if (lane == 0) out_loss[0] = 1.25f * (s / 8388608.0f);
    }
}

// ---------------------------------------------------------------------------
extern "C" void kernel_launch(void* const* d_in, const int* in_sizes, int n_in,
                              void* d_out, int out_size)
{
    const float* z_e = (const float*)d_in[0];
    const float* emb = (const float*)d_in[1];

    float* out  = (float*)d_out;
    float* res  = out;
    float* loss = out + 8388608;
    float* idxf = out + 8388609;

    cudaFuncSetAttribute(k_mma,  cudaFuncAttributeMaxDynamicSharedMemorySize, SMEM_MMA);
    cudaFuncSetAttribute(k_post, cudaFuncAttributeMaxDynamicSharedMemorySize, SMEM_POST);

    k_zero <<<1, 32>>>();
    k_prep <<<128, 256>>>(emb);
    k_mma  <<<dim3(NCB, N_ROWS / 128), 256, SMEM_MMA>>>(z_e);
    k_post <<<N_ROWS / 128, 256, SMEM_POST>>>(z_e, emb, res, idxf, loss);
}

// round 16
// speedup vs baseline: 1.6831x; 1.0749x over previous
#include <cuda_runtime.h>
#include <cstdint>
#include <cfloat>

typedef unsigned int u32;

#define N_ROWS  32768
#define C_DIM   256
#define K_CODES 1024
#define NCB     8          // code-blocks of 128
#define NCHUNK  8          // chunks of 32 c (K logical = 256, hi*hi only)
#define E2      0.5f       // 2*E; validated R7-R15
#define NSTAGE  3
#define A_STRIDE 132
#define A_FLOATS (32 * A_STRIDE)          // 4224
#define A_BYTES  (A_FLOATS * 4)           // 16896
#define STAGE_BYTES (A_BYTES + 16384)     // 33280
#define SMEM_MMA (NSTAGE * STAGE_BYTES)   // 99840 -> 2 CTAs/SM; also holds dist[128][133]
#define DSTRIDE 133                       // scan banks (5r+k)%32: conflict-free
#define SMEM_POST (64 * 257 * 4)          // 65792 -> 2 CTAs/SM

// efr: [code_tile(128)][kt(32)][lane 32][reg 2]  (tf32 hi of -2*emb)
__device__ float efr[(size_t)(K_CODES / 8) * 32 * 64];
__device__ float embT[C_DIM * K_CODES];    // [c][k] = -2*emb[k][c], exact fp32
__device__ float g_enorm[K_CODES];
__device__ float4 g_tv4[NCB * N_ROWS];     // per (cb,row): top-4 approx dists (sorted)
__device__ int4   g_ti4[NCB * N_ROWS];     // matching code indices
__device__ float g_partial[256];           // per-post-block sum of chosen dist
__device__ float g_zsq[256];               // per-rowblock sum ||z||^2 (from k_mma cb==0)
__device__ int   g_done;

// ---------------- helpers ----------------
__device__ __forceinline__ u32 smem_u32(const void* p) {
    return (u32)__cvta_generic_to_shared(p);
}
__device__ __forceinline__ void cp16(u32 dst, const void* src) {
    asm volatile("cp.async.cg.shared.global [%0], [%1], 16;" :: "r"(dst), "l"(src));
}
__device__ __forceinline__ u32 tf32u(float v) {
    u32 r; asm("cvt.rna.satfinite.tf32.f32 %0, %1;" : "=r"(r) : "f"(v));
    return r;
}
__device__ __forceinline__ void mma8(float* d, uint4 a, uint2 b) {
    asm("mma.sync.aligned.m16n8k8.row.col.f32.tf32.tf32.f32 "
        "{%0,%1,%2,%3}, {%4,%5,%6,%7}, {%8,%9}, {%0,%1,%2,%3};"
        : "+f"(d[0]), "+f"(d[1]), "+f"(d[2]), "+f"(d[3])
        : "r"(a.x), "r"(a.y), "r"(a.z), "r"(a.w), "r"(b.x), "r"(b.y));
}
__device__ __forceinline__ bool lessp(float va, int ia, float vb, int ib) {
    return va < vb || (va == vb && ia < ib);
}
// constant-index sorted insert into bv[0..3] (ascending)
__device__ __forceinline__ void ins4(float v, int k, float* bv, int* bi) {
    if (lessp(v, k, bv[3], bi[3])) {
        bv[3] = v; bi[3] = k;
        if (lessp(bv[3], bi[3], bv[2], bi[2])) {
            float tv = bv[2]; bv[2] = bv[3]; bv[3] = tv;
            int ti = bi[2]; bi[2] = bi[3]; bi[3] = ti;
        }
        if (lessp(bv[2], bi[2], bv[1], bi[1])) {
            float tv = bv[1]; bv[1] = bv[2]; bv[2] = tv;
            int ti = bi[1]; bi[1] = bi[2]; bi[2] = ti;
        }
        if (lessp(bv[1], bi[1], bv[0], bi[0])) {
            float tv = bv[0]; bv[0] = bv[1]; bv[1] = tv;
            int ti = bi[0]; bi[0] = bi[1]; bi[1] = ti;
        }
    }
}
__device__ __forceinline__ void cswap(float& va, int& ia, float& vb, int& ib) {
    bool sw = lessp(vb, ib, va, ia);
    float v0 = sw ? vb : va, v1 = sw ? va : vb;
    int   i0 = sw ? ib : ia, i1 = sw ? ia : ib;
    va = v0; vb = v1; ia = i0; ib = i1;
}
__device__ __forceinline__ void sort4_bitonic(float* w, int* wi) {
    cswap(w[0], wi[0], w[2], wi[2]);
    cswap(w[1], wi[1], w[3], wi[3]);
    cswap(w[0], wi[0], w[1], wi[1]);
    cswap(w[2], wi[2], w[3], wi[3]);
}
// merge two sorted 4-lists -> sorted top-4 (constant indices)
__device__ __forceinline__ void merge4_arrays(const float* av, const int* ai,
                                              const float* bv, const int* bi,
                                              float* rv, int* ri) {
    #pragma unroll
    for (int t = 0; t < 4; t++) {
        bool tm = lessp(av[t], ai[t], bv[3 - t], bi[3 - t]);
        rv[t] = tm ? av[t] : bv[3 - t];
        ri[t] = tm ? ai[t] : bi[3 - t];
    }
    sort4_bitonic(rv, ri);
}

// ---------------------------------------------------------------------------
// zero: reset the loss-reduction counter (runs first every replay)
// ---------------------------------------------------------------------------
__global__ void k_zero() { if (threadIdx.x == 0) g_done = 0; }

// ---------------------------------------------------------------------------
// prep (emb only): efr fragments + embT + norms. 128 blocks of 8 codes.
// ---------------------------------------------------------------------------
__global__ void __launch_bounds__(256)
k_prep(const float* __restrict__ emb)
{
    const int tid = threadIdx.x;
    const int ct = blockIdx.x;        // code tile (8 codes)
    const int k0 = ct * 8;
    for (int j = tid; j < 2048; j += 256) {
        int within = j & 63, kt = j >> 6;
        int lane = within >> 1, reg = within & 1;
        int code = k0 + (lane >> 2);
        int cmod = kt * 8 + (lane & 3) + reg * 4;
        efr[(size_t)(ct * 32 + kt) * 64 + within] =
            __uint_as_float(tf32u(-2.0f * emb[code * C_DIM + cmod]));
    }
    for (int j = tid; j < 2048; j += 256) {
        int c = j >> 3, kk = j & 7;
        embT[c * K_CODES + k0 + kk] = -2.0f * emb[(k0 + kk) * C_DIM + c];
    }
    int wid = tid >> 5, lane = tid & 31;
    int code = k0 + wid;
    const float4* p = (const float4*)(emb + code * C_DIM);
    float4 a = p[lane];
    float4 b = p[lane + 32];
    float s = a.x*a.x + a.y*a.y + a.z*a.z + a.w*a.w
            + b.x*b.x + b.y*b.y + b.z*b.z + b.w*b.w;
    #pragma unroll
    for (int m = 16; m; m >>= 1) s += __shfl_xor_sync(0xffffffffu, s, m);
    if (lane == 0) g_enorm[code] = s;
}

// ---------------------------------------------------------------------------
// main: tf32 mma.sync GEMM (hi*hi); epilogue via smem dist matrix (register
// pressure decoupled from mainloop: d[] dies at the smem dump).
// CTA 128 rows x 128 codes, 8 warps (4 row x 2 col), warp tile 32x64.
// ---------------------------------------------------------------------------
__device__ __forceinline__ void load_chunk(u32 base, int buf, int ch,
                                           int b, int hw0, int cb, int tid,
                                           const float* __restrict__ z_e)
{
    u32 dst = base + (u32)buf * STAGE_BYTES;
    #pragma unroll
    for (int t2 = 0; t2 < 4; t2++) {           // A: 32 c x 128 rows, direct from z_e
        int t = tid + t2 * 256;
        int c = t >> 5, part = t & 31;
        cp16(dst + (u32)(c * (A_STRIDE * 4) + part * 16),
             z_e + (((size_t)(b * C_DIM + ch * 32 + c)) << 10) + hw0 + part * 4);
    }
    #pragma unroll
    for (int t2 = 0; t2 < 4; t2++) {           // B: 4kt x 16nt x 256B = 16KB
        int t = tid + t2 * 256;
        int tile = t >> 4, part = t & 15;
        int kt = tile >> 4, nt = tile & 15;
        cp16(dst + (u32)A_BYTES + (u32)((tile << 8) + (part << 4)),
             (const char*)efr + ((((size_t)(cb * 16 + nt) * 32 + ch * 4 + kt) << 8) + (part << 4)));
    }
    asm volatile("cp.async.commit_group;");
}

__global__ void __launch_bounds__(256, 2)
k_mma(const float* __restrict__ z_e)
{
    extern __shared__ float smf[];
    __shared__ float en_s[128];
    __shared__ float sd4[2][128][4];
    __shared__ int   si4[2][128][4];
    __shared__ float wsum2[8];

    const int tid = threadIdx.x;
    const int lane = tid & 31, wid = tid >> 5;
    const int warp_m = wid & 3, warp_n = wid >> 2;
    const int cb = blockIdx.x;             // fast dim -> L2 reuse of z_e
    const int rb = blockIdx.y;
    const int r0 = rb * 128;
    const int b = r0 >> 10, hw0 = r0 & 1023;
    const u32 base = smem_u32(smf);

    if (tid < 128) en_s[tid] = g_enorm[cb * 128 + tid];

    float d[2][8][4];
    #pragma unroll
    for (int m = 0; m < 2; m++)
        #pragma unroll
        for (int n = 0; n < 8; n++)
            #pragma unroll
            for (int q = 0; q < 4; q++) d[m][n][q] = 0.0f;

    load_chunk(base, 0, 0, b, hw0, cb, tid, z_e);
    load_chunk(base, 1, 1, b, hw0, cb, tid, z_e);

    const int frow = (lane >> 2);
    const int fc   = (lane & 3);
    float zsq = 0.0f;

    for (int ch = 0; ch < NCHUNK; ch++) {
        int buf = ch % NSTAGE;
        if (ch < NCHUNK - 1) asm volatile("cp.async.wait_group 1;");
        else                 asm volatile("cp.async.wait_group 0;");
        __syncthreads();
        if (ch + 2 < NCHUNK) load_chunk(base, (ch + 2) % NSTAGE, ch + 2, b, hw0, cb, tid, z_e);

        const float* aS = smf + buf * (STAGE_BYTES / 4);
        const float* bS = aS + A_FLOATS;

        if (cb == 0) {                     // exact sum ||z||^2 (1/8 of CTAs)
            #pragma unroll
            for (int t2 = 0; t2 < 16; t2++) {
                int j = tid + t2 * 256;
                float v = aS[(j >> 7) * A_STRIDE + (j & 127)];
                zsq = fmaf(v, v, zsq);
            }
        }

        #pragma unroll
        for (int kt = 0; kt < 4; kt++) {
            uint4 a[2];
            uint2 bf[8];
            #pragma unroll
            for (int m = 0; m < 2; m++) {
                int rbase = warp_m * 32 + m * 16 + frow;
                int cbase = kt * 8 + fc;
                a[m].x = tf32u(aS[ cbase      * A_STRIDE + rbase    ]);
                a[m].y = tf32u(aS[ cbase      * A_STRIDE + rbase + 8]);
                a[m].z = tf32u(aS[(cbase + 4) * A_STRIDE + rbase    ]);
                a[m].w = tf32u(aS[(cbase + 4) * A_STRIDE + rbase + 8]);
            }
            #pragma unroll
            for (int n = 0; n < 8; n++)
                bf[n] = *(const uint2*)(bS + (((kt * 16 + warp_n * 8 + n) << 6) + (lane << 1)));
            #pragma unroll
            for (int m = 0; m < 2; m++)
                #pragma unroll
                for (int n = 0; n < 8; n++)
                    mma8(d[m][n], a[m], bf[n]);
        }
    }

    // ---- epilogue A: dump dist = acc + ||e||^2 into smem (d dies here) ----
    __syncthreads();                       // all warps done with stage buffers
    {
        const int g = lane >> 2, tq = lane & 3;
        const int wm0 = warp_m * 32, wn0 = warp_n * 64;
        #pragma unroll
        for (int m = 0; m < 2; m++)
            #pragma unroll
            for (int n = 0; n < 8; n++)
                #pragma unroll
                for (int q = 0; q < 4; q++) {
                    int row = wm0 + m * 16 + ((q >> 1) << 3) + g;
                    int col = wn0 + n * 8 + 2 * tq + (q & 1);
                    smf[row * DSTRIDE + col] = d[m][n][q] + en_s[col];
                }
    }

    if (cb == 0) {
        #pragma unroll
        for (int m = 16; m; m >>= 1) zsq += __shfl_xor_sync(0xffffffffu, zsq, m);
        if (lane == 0) wsum2[wid] = zsq;
    }
    __syncthreads();

    // ---- epilogue B: each half-thread scans 64 codes of one row ----
    {
        const int r = tid & 127, half = tid >> 7;
        const float* dr = smf + r * DSTRIDE + half * 64;
        float bv[4] = {FLT_MAX, FLT_MAX, FLT_MAX, FLT_MAX};
        int   bi_[4] = {0x7fffffff, 0x7fffffff, 0x7fffffff, 0x7fffffff};
        const int kbase = cb * 128 + half * 64;
        #pragma unroll 8
        for (int k = 0; k < 64; k++)
            ins4(dr[k], kbase + k, bv, bi_);
        #pragma unroll
        for (int t = 0; t < 4; t++) {
            sd4[half][r][t] = bv[t];
            si4[half][r][t] = bi_[t];
        }
    }
    __syncthreads();
    if (tid < 128) {
        float av[4], bvv[4], rv[4]; int ai[4], bii[4], ri[4];
        #pragma unroll
        for (int t = 0; t < 4; t++) {
            av[t] = sd4[0][tid][t]; ai[t] = si4[0][tid][t];
            bvv[t] = sd4[1][tid][t]; bii[t] = si4[1][tid][t];
        }
        merge4_arrays(av, ai, bvv, bii, rv, ri);
        size_t o = (size_t)cb * N_ROWS + r0 + tid;
        g_tv4[o] = make_float4(rv[0], rv[1], rv[2], rv[3]);
        g_ti4[o] = make_int4(ri[0], ri[1], ri[2], ri[3]);
    }
    if (cb == 0 && tid == 0) {
        float s = 0.0f;
        #pragma unroll
        for (int w = 0; w < 8; w++) s += wsum2[w];
        g_zsq[rb] = s;
    }
}

// ---------------------------------------------------------------------------
// post: pick + candidate refine (<=16 cands) + rare full rescue + gather/res
// + fused loss. esm staged in 64-row halves -> 2 CTAs/SM.
// ---------------------------------------------------------------------------
__global__ void __launch_bounds__(256, 2)
k_post(const float* __restrict__ z_e, const float* __restrict__ emb,
       float* __restrict__ res, float* __restrict__ out_idx_f,
       float* __restrict__ out_loss)
{
    extern __shared__ float esm[];           // 64 x 257
    __shared__ int   idx_sm[128];
    __shared__ float dist_sm[128];
    __shared__ int   full_list[128];
    __shared__ int   ref_list[128];
    __shared__ int   cand[128][16];
    __shared__ int   ccnt[128];
    __shared__ int   nfull_s, nref_s;
    __shared__ float zrow[256];
    __shared__ float wd[8]; __shared__ int wk[8];
    __shared__ float wsum[8];
    __shared__ int   lastflag;

    const int tid = threadIdx.x;
    const int wid = tid >> 5, lane = tid & 31;
    const int r0 = blockIdx.x * 128;
    const int b = r0 >> 10, hw0 = r0 & 1023;

    if (tid == 0) { nfull_s = 0; nref_s = 0; }
    __syncthreads();

    // classify using top-4 lists
    if (tid < 128) {
        int row = r0 + tid;
        float V1 = FLT_MAX; int bi = 0x7fffffff;
        float4 vv[NCB]; int4 kk[NCB];
        #pragma unroll
        for (int cb = 0; cb < NCB; cb++) {
            vv[cb] = g_tv4[(size_t)cb * N_ROWS + row];
            kk[cb] = g_ti4[(size_t)cb * N_ROWS + row];
            if (lessp(vv[cb].x, kk[cb].x, V1, bi)) { V1 = vv[cb].x; bi = kk[cb].x; }
        }
        idx_sm[tid] = bi;
        dist_sm[tid] = V1;
        float th = V1 + E2;
        bool unc = false; int nc = 0;
        #pragma unroll
        for (int cb = 0; cb < NCB; cb++) {
            if (vv[cb].w < th) unc = true;       // 4th-best too close: coverage risk
            if (vv[cb].x < th) { if (nc < 16) cand[tid][nc] = kk[cb].x; nc++; }
            if (vv[cb].y < th) { if (nc < 16) cand[tid][nc] = kk[cb].y; nc++; }
            if (vv[cb].z < th) { if (nc < 16) cand[tid][nc] = kk[cb].z; nc++; }
            if (vv[cb].w < th) { if (nc < 16) cand[tid][nc] = kk[cb].w; nc++; }
        }
        if (nc > 16) unc = true;                 // candidate overflow -> full scan
        if (unc) {
            full_list[atomicAdd(&nfull_s, 1)] = tid;
        } else if (nc > 1) {
            int p = atomicAdd(&nref_s, 1);
            ref_list[p] = tid;
            ccnt[tid] = nc;
        }
    }
    __syncthreads();

    // candidate refine: warp per entry, exact fp32 (also yields exact dist)
    for (int j = wid; j < nref_s; j += 8) {
        int rl = ref_list[j];
        int hw = hw0 + rl;
        float zreg[8];
        #pragma unroll
        for (int cc = 0; cc < 8; cc++)
            zreg[cc] = z_e[(((size_t)(b * C_DIM + cc * 32 + lane)) << 10) + hw];
        int nc = ccnt[rl];
        float bd = FLT_MAX; int bk = 0x7fffffff;
        for (int ci = 0; ci < nc; ci++) {
            int k = cand[rl][ci];
            const float* er = emb + (size_t)k * C_DIM;
            float acc = 0.0f;
            #pragma unroll
            for (int cc = 0; cc < 8; cc++)
                acc += zreg[cc] * er[cc * 32 + lane];
            #pragma unroll
            for (int m = 16; m; m >>= 1) acc += __shfl_xor_sync(0xffffffffu, acc, m);
            float dd = g_enorm[k] - 2.0f * acc;
            if (dd < bd || (dd == bd && k < bk)) { bd = dd; bk = k; }
        }
        if (lane == 0) { idx_sm[rl] = bk; dist_sm[rl] = bd; }
    }

    // full-scan rescue (rare): block-cooperative via embT
    int nfull = nfull_s;
    for (int j = 0; j < nfull; j++) {
        int rl = full_list[j];
        __syncthreads();
        zrow[tid] = z_e[(((size_t)(b * C_DIM + tid)) << 10) + hw0 + rl];
        __syncthreads();
        float bd = FLT_MAX; int bk = 0x7fffffff;
        #pragma unroll
        for (int gch = 0; gch < 4; gch++) {
            int k = wid * 128 + gch * 32 + lane;
            float acc = 0.0f;
            #pragma unroll 8
            for (int c = 0; c < C_DIM; c++)
                acc = fmaf(zrow[c], embT[c * K_CODES + k], acc);
            float dd = g_enorm[k] + acc;
            if (dd < bd) { bd = dd; bk = k; }   // k increasing -> ties keep lower k
        }
        #pragma unroll
        for (int m = 16; m; m >>= 1) {
            float obd = __shfl_xor_sync(0xffffffffu, bd, m);
            int   obk = __shfl_xor_sync(0xffffffffu, bk, m);
            if (obd < bd || (obd == bd && obk < bk)) { bd = obd; bk = obk; }
        }
        if (lane == 0) { wd[wid] = bd; wk[wid] = bk; }
        __syncthreads();
        if (tid == 0) {
            float B = FLT_MAX; int K = 0x7fffffff;
            #pragma unroll
            for (int w = 0; w < 8; w++)
                if (wd[w] < B || (wd[w] == B && wk[w] < K)) { B = wd[w]; K = wk[w]; }
            idx_sm[rl] = K;
            dist_sm[rl] = B;
        }
    }
    __syncthreads();

    if (tid < 128) out_idx_f[r0 + tid] = (float)idx_sm[tid];

    // gather + res write in 2 halves of 64 rows (smaller smem -> 2 CTAs/SM)
    for (int hp = 0; hp < 2; hp++) {
        const int rbase = hp * 64;
        __syncthreads();
        for (int i = tid; i < 64 * 256; i += 256) {
            int r = i >> 8, c = i & 255;
            esm[r * 257 + c] = emb[idx_sm[rbase + r] * C_DIM + c];
        }
        __syncthreads();
        const int r = tid & 63, cq = tid >> 6;
        for (int cc = 0; cc < 256; cc += 4) {
            int c = cc + cq;
            res[(((size_t)(b * C_DIM + c)) << 10) + hw0 + rbase + r] = esm[r * 257 + c];
        }
    }

    // loss partial: sum of chosen distances over this block's rows
    float dv = (tid < 128) ? dist_sm[tid] : 0.0f;
    #pragma unroll
    for (int m = 16; m; m >>= 1) dv += __shfl_xor_sync(0xffffffffu, dv, m);
    if (lane == 0) wsum[wid] = dv;
    __syncthreads();
    if (tid == 0) {
        float s = 0.0f;
        #pragma unroll
        for (int w = 0; w < 8; w++) s += wsum[w];
        g_partial[blockIdx.x] = s;
        __threadfence();
        lastflag = (atomicAdd(&g_done, 1) == 255) ? 1 : 0;
    }
    __syncthreads();
    if (lastflag && wid == 0) {
        __threadfence();
        float s = 0.0f;
        for (int j = lane; j < 256; j += 32) s += g_partial[j] + g_zsq[j];
        #pragma unroll
        for (int m = 16; m; m >>= 1) s += __shfl_xor_sync(0xffffffffu, s, m);
        if (lane == 0) out_loss[0] = 1.25f * (s / 8388608.0f);
    }
}

// ---------------------------------------------------------------------------
extern "C" void kernel_launch(void* const* d_in, const int* in_sizes, int n_in,
                              void* d_out, int out_size)
{
    const float* z_e = (const float*)d_in[0];
    const float* emb = (const float*)d_in[1];

    float* out  = (float*)d_out;
    float* res  = out;
    float* loss = out + 8388608;
    float* idxf = out + 8388609;

    cudaFuncSetAttribute(k_mma,  cudaFuncAttributeMaxDynamicSharedMemorySize, SMEM_MMA);
    cudaFuncSetAttribute(k_post, cudaFuncAttributeMaxDynamicSharedMemorySize, SMEM_POST);

    k_zero <<<1, 32>>>();
    k_prep <<<128, 256>>>(emb);
    k_mma  <<<dim3(NCB, N_ROWS / 128), 256, SMEM_MMA>>>(z_e);
    k_post <<<N_ROWS / 128, 256, SMEM_POST>>>(z_e, emb, res, idxf, loss);
}